// round 1
// baseline (speedup 1.0000x reference)
#include <cuda_runtime.h>
#include <cuda_bf16.h>
#include <math.h>

// ---------------- problem constants ----------------
#define BATCH   4
#define SEQ     1500
#define CDIM    1024
#define NHEAD   16
#define HDIM    64
#define FDIM    4096
#define ADIM    256
#define MROWS   (BATCH * SEQ)          // 6000
#define QKSCALE 0.35355339059327379f   // 64^-0.25

// ---------------- scratch (device globals; no allocation allowed) ----------------
__device__ float g_h [MROWS * CDIM];   // LN output (reused for both LNs)
__device__ float g_q [MROWS * CDIM];   // [B,H,S,D]
__device__ float g_k [MROWS * CDIM];   // [B,H,S,D]
__device__ float g_v [MROWS * CDIM];   // [B,H,S,D]
__device__ float g_at[MROWS * CDIM];   // attention out, [B,S,H*D]
__device__ float g_x1[MROWS * CDIM];   // x after attention residual
__device__ float g_ff[MROWS * FDIM];   // MLP hidden
__device__ float g_ds[MROWS * ADIM];   // adapter hidden

// ---------------- helpers ----------------
__device__ __forceinline__ float gelu_exact(float v) {
    return 0.5f * v * (1.0f + erff(v * 0.70710678118654752f));
}

// ---------------- LayerNorm: one block per row of 1024 ----------------
__global__ __launch_bounds__(256) void ln_kernel(const float* __restrict__ x,
                                                 const float* __restrict__ w,
                                                 const float* __restrict__ b,
                                                 float* __restrict__ out) {
    __shared__ float red[2][8];
    const int row = blockIdx.x;
    const int tid = threadIdx.x;
    const int lane = tid & 31, wid = tid >> 5;

    float4 v = reinterpret_cast<const float4*>(x + (size_t)row * CDIM)[tid];
    float s  = v.x + v.y + v.z + v.w;
    float ss = v.x*v.x + v.y*v.y + v.z*v.z + v.w*v.w;
    #pragma unroll
    for (int o = 16; o; o >>= 1) {
        s  += __shfl_xor_sync(0xffffffffu, s,  o);
        ss += __shfl_xor_sync(0xffffffffu, ss, o);
    }
    if (lane == 0) { red[0][wid] = s; red[1][wid] = ss; }
    __syncthreads();
    float fs = 0.f, fss = 0.f;
    #pragma unroll
    for (int i = 0; i < 8; i++) { fs += red[0][i]; fss += red[1][i]; }
    const float mu  = fs * (1.0f / CDIM);
    const float var = fss * (1.0f / CDIM) - mu * mu;
    const float r   = rsqrtf(var + 1e-5f);

    float4 wv = reinterpret_cast<const float4*>(w)[tid];
    float4 bv = reinterpret_cast<const float4*>(b)[tid];
    float4 ov;
    ov.x = (v.x - mu) * r * wv.x + bv.x;
    ov.y = (v.y - mu) * r * wv.y + bv.y;
    ov.z = (v.z - mu) * r * wv.z + bv.z;
    ov.w = (v.w - mu) * r * wv.w + bv.w;
    reinterpret_cast<float4*>(out + (size_t)row * CDIM)[tid] = ov;
}

// ---------------- SGEMM: out[M,N] = A[M,K] @ B[N,K]^T (+bias) (+epilogue) ----------------
// MODE 0: out = acc + bias + res           (plain / residual)
// MODE 1: out = gelu(acc + bias)
// MODE 2: out[((b*H+h)*S+s)*D+d] = (acc + bias) * scale   (QKV transposed write)
template<int MODE>
__global__ __launch_bounds__(256) void sgemm(const float* __restrict__ A,
                                             const float* __restrict__ B,
                                             const float* __restrict__ bias,
                                             const float* __restrict__ res,
                                             float* __restrict__ out,
                                             int M, int N, int K, float scale) {
    __shared__ float As[8][128];
    __shared__ float Bs[8][128];

    const int tid  = threadIdx.x;
    const int bm   = blockIdx.y * 128;
    const int bn   = blockIdx.x * 128;
    const int arow = tid >> 1;            // 0..127
    const int acol = (tid & 1) * 4;       // 0 or 4
    const int tx   = tid & 15;            // 0..15 -> columns tx*4 and 64+tx*4
    const int ty   = tid >> 4;            // 0..15 -> rows ty*8..+7

    const bool aval = (bm + arow) < M;
    const float* Aptr = A + (size_t)(bm + arow) * K + acol;
    const float* Bptr = B + (size_t)(bn + arow) * K + acol;

    float acc[8][8];
    #pragma unroll
    for (int i = 0; i < 8; i++)
        #pragma unroll
        for (int j = 0; j < 8; j++) acc[i][j] = 0.f;

    for (int k0 = 0; k0 < K; k0 += 8) {
        float4 av = aval ? *reinterpret_cast<const float4*>(Aptr + k0)
                         : make_float4(0.f, 0.f, 0.f, 0.f);
        float4 bv = *reinterpret_cast<const float4*>(Bptr + k0);
        As[acol + 0][arow] = av.x; As[acol + 1][arow] = av.y;
        As[acol + 2][arow] = av.z; As[acol + 3][arow] = av.w;
        Bs[acol + 0][arow] = bv.x; Bs[acol + 1][arow] = bv.y;
        Bs[acol + 2][arow] = bv.z; Bs[acol + 3][arow] = bv.w;
        __syncthreads();

        #pragma unroll
        for (int k = 0; k < 8; k++) {
            float4 a0 = *reinterpret_cast<const float4*>(&As[k][ty * 8]);
            float4 a1 = *reinterpret_cast<const float4*>(&As[k][ty * 8 + 4]);
            float4 b0 = *reinterpret_cast<const float4*>(&Bs[k][tx * 4]);
            float4 b1 = *reinterpret_cast<const float4*>(&Bs[k][tx * 4 + 64]);
            float ar[8] = {a0.x, a0.y, a0.z, a0.w, a1.x, a1.y, a1.z, a1.w};
            float br[8] = {b0.x, b0.y, b0.z, b0.w, b1.x, b1.y, b1.z, b1.w};
            #pragma unroll
            for (int i = 0; i < 8; i++)
                #pragma unroll
                for (int j = 0; j < 8; j++) acc[i][j] += ar[i] * br[j];
        }
        __syncthreads();
    }

    // epilogue
    #pragma unroll
    for (int i = 0; i < 8; i++) {
        const int m = bm + ty * 8 + i;
        if (m >= M) break;
        int bI = 0, sI = 0;
        if (MODE == 2) { bI = m / SEQ; sI = m - bI * SEQ; }
        #pragma unroll
        for (int hh = 0; hh < 2; hh++) {
            #pragma unroll
            for (int j = 0; j < 4; j++) {
                const int n = bn + hh * 64 + tx * 4 + j;
                float vv = acc[i][hh * 4 + j];
                if (bias) vv += bias[n];
                if (MODE == 0) {
                    if (res) vv += res[(size_t)m * N + n];
                    out[(size_t)m * N + n] = vv;
                } else if (MODE == 1) {
                    out[(size_t)m * N + n] = gelu_exact(vv);
                } else {
                    vv *= scale;
                    const int hd = n >> 6, dd = n & 63;
                    out[(((size_t)bI * NHEAD + hd) * SEQ + sI) * HDIM + dd] = vv;
                }
            }
        }
    }
}

// ---------------- attention: one thread per q row, flash-style ----------------
// Q,K,V in [B,H,S,D]; O written in [B,S,H*D]
__global__ __launch_bounds__(128) void attn_kernel(const float* __restrict__ Q,
                                                   const float* __restrict__ Kp,
                                                   const float* __restrict__ V,
                                                   float* __restrict__ O) {
    __shared__ float ks[32 * 64];
    __shared__ float vs[32 * 64];

    const int b = blockIdx.z, h = blockIdx.y;
    const int qrow = blockIdx.x * 128 + threadIdx.x;
    const size_t base = (size_t)(b * NHEAD + h) * SEQ * HDIM;
    const bool valid = qrow < SEQ;

    float q[64], o[64];
    #pragma unroll
    for (int d = 0; d < 64; d++) o[d] = 0.f;
    if (valid) {
        #pragma unroll
        for (int d4 = 0; d4 < 16; d4++) {
            float4 t = *reinterpret_cast<const float4*>(Q + base + (size_t)qrow * 64 + d4 * 4);
            q[d4*4+0] = t.x; q[d4*4+1] = t.y; q[d4*4+2] = t.z; q[d4*4+3] = t.w;
        }
    } else {
        #pragma unroll
        for (int d = 0; d < 64; d++) q[d] = 0.f;
    }

    float mmax = -1e30f, l = 0.f;
    const int ntiles = (SEQ + 31) / 32;   // 47

    for (int t = 0; t < ntiles; t++) {
        const int j0 = t * 32;
        // cooperative load of K/V tile (32 rows x 64)
        #pragma unroll
        for (int r = 0; r < 4; r++) {
            const int fi = r * 512 + threadIdx.x * 4;
            const int jj = fi >> 6;
            float4 kv, vv;
            if (j0 + jj < SEQ) {
                kv = *reinterpret_cast<const float4*>(Kp + base + (size_t)j0 * 64 + fi);
                vv = *reinterpret_cast<const float4*>(V  + base + (size_t)j0 * 64 + fi);
            } else {
                kv = make_float4(0.f, 0.f, 0.f, 0.f);
                vv = kv;
            }
            *reinterpret_cast<float4*>(&ks[fi]) = kv;
            *reinterpret_cast<float4*>(&vs[fi]) = vv;
        }
        __syncthreads();

        float sc[32];
        float tmax = -1e30f;
        #pragma unroll
        for (int jj = 0; jj < 32; jj++) {
            float s = 0.f;
            #pragma unroll
            for (int d4 = 0; d4 < 16; d4++) {
                float4 kv = *reinterpret_cast<const float4*>(&ks[jj * 64 + d4 * 4]);
                s += q[d4*4+0]*kv.x + q[d4*4+1]*kv.y + q[d4*4+2]*kv.z + q[d4*4+3]*kv.w;
            }
            if (j0 + jj >= SEQ) s = -1e30f;
            sc[jj] = s;
            tmax = fmaxf(tmax, s);
        }
        const float nm = fmaxf(mmax, tmax);
        const float corr = __expf(mmax - nm);
        l *= corr;
        #pragma unroll
        for (int d = 0; d < 64; d++) o[d] *= corr;
        #pragma unroll
        for (int jj = 0; jj < 32; jj++) {
            const float p = __expf(sc[jj] - nm);
            l += p;
            #pragma unroll
            for (int d4 = 0; d4 < 16; d4++) {
                float4 vv = *reinterpret_cast<const float4*>(&vs[jj * 64 + d4 * 4]);
                o[d4*4+0] += p * vv.x; o[d4*4+1] += p * vv.y;
                o[d4*4+2] += p * vv.z; o[d4*4+3] += p * vv.w;
            }
        }
        mmax = nm;
        __syncthreads();
    }

    if (valid) {
        const float inv = 1.0f / l;
        float* op = O + ((size_t)(b * SEQ + qrow)) * CDIM + h * HDIM;
        #pragma unroll
        for (int d4 = 0; d4 < 16; d4++) {
            float4 ov;
            ov.x = o[d4*4+0]*inv; ov.y = o[d4*4+1]*inv;
            ov.z = o[d4*4+2]*inv; ov.w = o[d4*4+3]*inv;
            *reinterpret_cast<float4*>(op + d4 * 4) = ov;
        }
    }
}

// ---------------- launch ----------------
extern "C" void kernel_launch(void* const* d_in, const int* in_sizes, int n_in,
                              void* d_out, int out_size) {
    const float* x        = (const float*)d_in[0];
    const float* Wq       = (const float*)d_in[1];
    const float* bq       = (const float*)d_in[2];
    const float* Wk       = (const float*)d_in[3];
    const float* Wv       = (const float*)d_in[4];
    const float* bv       = (const float*)d_in[5];
    const float* Wo       = (const float*)d_in[6];
    const float* bo       = (const float*)d_in[7];
    const float* ln_aw    = (const float*)d_in[8];
    const float* ln_ab    = (const float*)d_in[9];
    const float* W1       = (const float*)d_in[10];
    const float* b1       = (const float*)d_in[11];
    const float* W2       = (const float*)d_in[12];
    const float* b2       = (const float*)d_in[13];
    const float* ln_mw    = (const float*)d_in[14];
    const float* ln_mb    = (const float*)d_in[15];
    const float* Wds      = (const float*)d_in[16];
    const float* bds      = (const float*)d_in[17];
    const float* Wus      = (const float*)d_in[18];
    const float* bus      = (const float*)d_in[19];
    float* out = (float*)d_out;

    float *h, *q, *k, *v, *at, *x1, *ff, *ds;
    cudaGetSymbolAddress((void**)&h,  g_h);
    cudaGetSymbolAddress((void**)&q,  g_q);
    cudaGetSymbolAddress((void**)&k,  g_k);
    cudaGetSymbolAddress((void**)&v,  g_v);
    cudaGetSymbolAddress((void**)&at, g_at);
    cudaGetSymbolAddress((void**)&x1, g_x1);
    cudaGetSymbolAddress((void**)&ff, g_ff);
    cudaGetSymbolAddress((void**)&ds, g_ds);

    const int mgrid = (MROWS + 127) / 128;            // 47
    dim3 gC (CDIM / 128, mgrid);                      // (8, 47)
    dim3 gF (FDIM / 128, mgrid);                      // (32, 47)
    dim3 gA (ADIM / 128, mgrid);                      // (2, 47)
    dim3 gAt((SEQ + 127) / 128, NHEAD, BATCH);        // (12, 16, 4)

    // attention
    ln_kernel<<<MROWS, 256>>>(x, ln_aw, ln_ab, h);
    sgemm<2><<<gC, 256>>>(h, Wq, bq,      nullptr, q,  MROWS, CDIM, CDIM, QKSCALE);
    sgemm<2><<<gC, 256>>>(h, Wk, nullptr, nullptr, k,  MROWS, CDIM, CDIM, QKSCALE);
    sgemm<2><<<gC, 256>>>(h, Wv, bv,      nullptr, v,  MROWS, CDIM, CDIM, 1.0f);
    attn_kernel<<<gAt, 128>>>(q, k, v, at);
    sgemm<0><<<gC, 256>>>(at, Wo, bo, x, x1, MROWS, CDIM, CDIM, 1.0f);

    // MLP
    ln_kernel<<<MROWS, 256>>>(x1, ln_mw, ln_mb, h);
    sgemm<1><<<gF, 256>>>(h,  W1, b1, nullptr, ff,  MROWS, FDIM, CDIM, 1.0f);
    sgemm<0><<<gC, 256>>>(ff, W2, b2, x1,      out, MROWS, CDIM, FDIM, 1.0f);

    // bottleneck adapter
    sgemm<1><<<gA, 256>>>(out, Wds, bds, nullptr, ds,  MROWS, ADIM, CDIM, 1.0f);
    sgemm<0><<<gC, 256>>>(ds,  Wus, bus, out,     out, MROWS, CDIM, ADIM, 1.0f);
}

// round 3
// speedup vs baseline: 1.4950x; 1.4950x over previous
#include <cuda_runtime.h>
#include <cuda_bf16.h>
#include <math.h>
#include <stdint.h>

// ---------------- problem constants ----------------
#define BATCH   4
#define SEQ     1500
#define CDIM    1024
#define NHEAD   16
#define HDIM    64
#define FDIM    4096
#define ADIM    256
#define MROWS   (BATCH * SEQ)          // 6000
#define QKSCALE 0.35355339059327379f   // 64^-0.25

// ---------------- scratch ----------------
__device__ float g_q [MROWS * CDIM];   // [B,H,S,D]
__device__ float g_k [MROWS * CDIM];
__device__ float g_v [MROWS * CDIM];
__device__ float g_x1[MROWS * CDIM];

__device__ __nv_bfloat16 g_Hh[MROWS * CDIM];
__device__ __nv_bfloat16 g_Hl[MROWS * CDIM];
__device__ __nv_bfloat16 g_Fh[MROWS * FDIM];
__device__ __nv_bfloat16 g_Fl[MROWS * FDIM];
__device__ __nv_bfloat16 g_Dh[MROWS * ADIM];
__device__ __nv_bfloat16 g_Dl[MROWS * ADIM];

#define CC      (CDIM * CDIM)
#define W1SZ    (FDIM * CDIM)
#define ASZ     (ADIM * CDIM)
#define OFF_WQ  0
#define OFF_WK  (CC)
#define OFF_WV  (2 * CC)
#define OFF_WO  (3 * CC)
#define OFF_W1  (4 * CC)
#define OFF_W2  (4 * CC + W1SZ)
#define OFF_WDS (4 * CC + 2 * W1SZ)
#define OFF_WUS (4 * CC + 2 * W1SZ + ASZ)
#define WTOT    (4 * CC + 2 * W1SZ + 2 * ASZ)
__device__ __nv_bfloat16 g_Wh[WTOT];
__device__ __nv_bfloat16 g_Wl[WTOT];

// ---------------- helpers ----------------
__device__ __forceinline__ float gelu_exact(float v) {
    return 0.5f * v * (1.0f + erff(v * 0.70710678118654752f));
}
__device__ __forceinline__ void split2(float x, __nv_bfloat16& h, __nv_bfloat16& l) {
    h = __float2bfloat16(x);
    l = __float2bfloat16(x - __bfloat162float(h));
}
__device__ __forceinline__ uint32_t smem_u32(const void* p) {
    uint32_t a;
    asm("{ .reg .u64 t; cvta.to.shared.u64 t, %1; cvt.u32.u64 %0, t; }" : "=r"(a) : "l"(p));
    return a;
}
__device__ __forceinline__ void cp_async16(uint32_t dst, const void* src) {
    asm volatile("cp.async.cg.shared.global [%0], [%1], 16;" :: "r"(dst), "l"(src));
}
__device__ __forceinline__ void ldsm_x4(uint32_t& r0, uint32_t& r1, uint32_t& r2,
                                        uint32_t& r3, uint32_t addr) {
    asm volatile("ldmatrix.sync.aligned.m8n8.x4.shared.b16 {%0,%1,%2,%3}, [%4];"
        : "=r"(r0), "=r"(r1), "=r"(r2), "=r"(r3) : "r"(addr));
}
__device__ __forceinline__ void mma_bf16(float* c, const uint32_t* a, const uint32_t* b) {
    asm volatile("mma.sync.aligned.m16n8k16.row.col.f32.bf16.bf16.f32 "
        "{%0,%1,%2,%3}, {%4,%5,%6,%7}, {%8,%9}, {%0,%1,%2,%3};"
        : "+f"(c[0]), "+f"(c[1]), "+f"(c[2]), "+f"(c[3])
        : "r"(a[0]), "r"(a[1]), "r"(a[2]), "r"(a[3]), "r"(b[0]), "r"(b[1]));
}

// ---------------- split kernels ----------------
__global__ __launch_bounds__(256) void split_kernel(const float* __restrict__ s,
                                                    __nv_bfloat16* __restrict__ h,
                                                    __nv_bfloat16* __restrict__ l,
                                                    int n4) {
    int i = blockIdx.x * 256 + threadIdx.x;
    if (i >= n4) return;
    float4 v = reinterpret_cast<const float4*>(s)[i];
    __nv_bfloat16 h0, h1, h2, h3, l0, l1, l2, l3;
    split2(v.x, h0, l0); split2(v.y, h1, l1);
    split2(v.z, h2, l2); split2(v.w, h3, l3);
    __nv_bfloat162* hp = reinterpret_cast<__nv_bfloat162*>(h + (size_t)i * 4);
    __nv_bfloat162* lp = reinterpret_cast<__nv_bfloat162*>(l + (size_t)i * 4);
    hp[0] = __nv_bfloat162(h0, h1); hp[1] = __nv_bfloat162(h2, h3);
    lp[0] = __nv_bfloat162(l0, l1); lp[1] = __nv_bfloat162(l2, l3);
}

__global__ __launch_bounds__(256) void ln_split_kernel(const float* __restrict__ x,
                                                       const float* __restrict__ w,
                                                       const float* __restrict__ b,
                                                       __nv_bfloat16* __restrict__ oh,
                                                       __nv_bfloat16* __restrict__ ol) {
    __shared__ float red[2][8];
    const int row = blockIdx.x;
    const int tid = threadIdx.x;
    const int lane = tid & 31, wid = tid >> 5;

    float4 v = reinterpret_cast<const float4*>(x + (size_t)row * CDIM)[tid];
    float s  = v.x + v.y + v.z + v.w;
    float ss = v.x*v.x + v.y*v.y + v.z*v.z + v.w*v.w;
    #pragma unroll
    for (int o = 16; o; o >>= 1) {
        s  += __shfl_xor_sync(0xffffffffu, s,  o);
        ss += __shfl_xor_sync(0xffffffffu, ss, o);
    }
    if (lane == 0) { red[0][wid] = s; red[1][wid] = ss; }
    __syncthreads();
    float fs = 0.f, fss = 0.f;
    #pragma unroll
    for (int i = 0; i < 8; i++) { fs += red[0][i]; fss += red[1][i]; }
    const float mu  = fs * (1.0f / CDIM);
    const float var = fss * (1.0f / CDIM) - mu * mu;
    const float r   = rsqrtf(var + 1e-5f);

    float4 wv = reinterpret_cast<const float4*>(w)[tid];
    float4 bv = reinterpret_cast<const float4*>(b)[tid];
    float o0 = (v.x - mu) * r * wv.x + bv.x;
    float o1 = (v.y - mu) * r * wv.y + bv.y;
    float o2 = (v.z - mu) * r * wv.z + bv.z;
    float o3 = (v.w - mu) * r * wv.w + bv.w;
    __nv_bfloat16 h0,h1,h2,h3,l0,l1,l2,l3;
    split2(o0,h0,l0); split2(o1,h1,l1); split2(o2,h2,l2); split2(o3,h3,l3);
    size_t base = (size_t)row * CDIM + tid * 4;
    __nv_bfloat162* hp = reinterpret_cast<__nv_bfloat162*>(oh + base);
    __nv_bfloat162* lp = reinterpret_cast<__nv_bfloat162*>(ol + base);
    hp[0] = __nv_bfloat162(h0, h1); hp[1] = __nv_bfloat162(h2, h3);
    lp[0] = __nv_bfloat162(l0, l1); lp[1] = __nv_bfloat162(l2, l3);
}

// ---------------- split-bf16 tensor-core GEMM (mma.sync) ----------------
// out[M,N] = A[M,K] @ B[N,K]^T using Ah*Bh + Ah*Bl + Al*Bh.
// MODE 0: v = acc+bias(+res) -> fp32 out (optional SPLIT bf16 out)
// MODE 1: v = gelu(acc+bias) -> split bf16 out
// MODE 2: v = (acc+bias)*scale -> fp32 out transposed to [B,H,S,D]
#define BK 64
#define TILEB  (128 * BK * 2)         // 16384 bytes
#define STAGEB (4 * TILEB)            // 65536
#define GEMM_SMEM (2 * STAGEB)        // 131072

template<int MODE, bool SPLIT>
__global__ __launch_bounds__(256, 1) void gemm_mma(
        const __nv_bfloat16* __restrict__ Ah, const __nv_bfloat16* __restrict__ Al,
        const __nv_bfloat16* __restrict__ Bh, const __nv_bfloat16* __restrict__ Bl,
        const float* __restrict__ bias, const float* __restrict__ res,
        float* __restrict__ out,
        __nv_bfloat16* __restrict__ Oh, __nv_bfloat16* __restrict__ Ol,
        int M, int N, int K, float scale) {
    extern __shared__ char smem[];
    const uint32_t sbase = smem_u32(smem);
    const int tid  = threadIdx.x;
    const int warp = tid >> 5, lane = tid & 31;
    const int bm = blockIdx.y * 128, bn = blockIdx.x * 128;
    const int wm = warp & 3, wn = warp >> 2;   // 4 x 2 warp grid: 32 x 64 per warp

    // ---- loader mapping: 4 tiles (Ah,Al,Bh,Bl) x 64 threads, 2 rows each ----
    const int ltile = tid >> 6;
    const int lrow0 = (tid & 63) * 2;
    const __nv_bfloat16* lsrc = (ltile == 0) ? Ah : (ltile == 1) ? Al
                              : (ltile == 2) ? Bh : Bl;
    const bool isA = (ltile < 2);
    int gr0 = isA ? (bm + lrow0) : (bn + lrow0);
    int gr1 = gr0 + 1;
    if (isA) { gr0 = min(gr0, M - 1); gr1 = min(gr1, M - 1); }
    const __nv_bfloat16* src0 = lsrc + (size_t)gr0 * K;
    const __nv_bfloat16* src1 = lsrc + (size_t)gr1 * K;
    const uint32_t dtile = sbase + ltile * TILEB;
    // precomputed swizzled dest offsets for the two rows
    uint32_t d0[8], d1[8];
    #pragma unroll
    for (int c = 0; c < 8; c++) {
        d0[c] = (uint32_t)((lrow0 * 8 + (c ^ (lrow0 & 7))) * 16);
        d1[c] = (uint32_t)(((lrow0 + 1) * 8 + (c ^ ((lrow0 + 1) & 7))) * 16);
    }

    float acc[2][8][4];
    #pragma unroll
    for (int a = 0; a < 2; a++)
        #pragma unroll
        for (int b = 0; b < 8; b++)
            #pragma unroll
            for (int c = 0; c < 4; c++) acc[a][b][c] = 0.f;

    const int nch = K / BK;

    // prologue: load chunk 0 -> stage 0
    {
        const uint32_t db = dtile;
        #pragma unroll
        for (int c = 0; c < 8; c++) {
            cp_async16(db + d0[c], src0 + c * 8);
            cp_async16(db + d1[c], src1 + c * 8);
        }
        asm volatile("cp.async.commit_group;");
    }

    // ldmatrix source addresses (A: 2 m-tiles; B: 4 n-pair-tiles), per k-step
    const int arow = (lane & 15);
    const int acsel = lane >> 4;                 // 0 or 1 -> chunk half
    const int brow = (lane & 7) + ((lane >> 4) & 1) * 8;
    const int bcsel = (lane >> 3) & 1;

    for (int kc = 0; kc < nch; kc++) {
        const int st = kc & 1;
        if (kc + 1 < nch) {
            const uint32_t db = dtile + (st ^ 1) * STAGEB;
            const int k0 = (kc + 1) * BK;
            #pragma unroll
            for (int c = 0; c < 8; c++) {
                cp_async16(db + d0[c], src0 + k0 + c * 8);
                cp_async16(db + d1[c], src1 + k0 + c * 8);
            }
            asm volatile("cp.async.commit_group;");
            asm volatile("cp.async.wait_group 1;");
        } else {
            asm volatile("cp.async.wait_group 0;");
        }
        __syncthreads();

        const uint32_t base  = sbase + st * STAGEB;
        const uint32_t ahB = base, alB = base + TILEB;
        const uint32_t bhB = base + 2 * TILEB, blB = base + 3 * TILEB;

        #pragma unroll
        for (int ks = 0; ks < 4; ks++) {
            uint32_t ah[2][4], al[2][4], bh[8][2], bl[8][2];
            #pragma unroll
            for (int mt = 0; mt < 2; mt++) {
                const int row = wm * 32 + mt * 16 + arow;
                const int ch  = ks * 2 + acsel;
                const uint32_t off = (uint32_t)((row * 8 + (ch ^ (row & 7))) * 16);
                ldsm_x4(ah[mt][0], ah[mt][1], ah[mt][2], ah[mt][3], ahB + off);
                ldsm_x4(al[mt][0], al[mt][1], al[mt][2], al[mt][3], alB + off);
            }
            #pragma unroll
            for (int np = 0; np < 4; np++) {
                const int row = wn * 64 + np * 16 + brow;
                const int ch  = ks * 2 + bcsel;
                const uint32_t off = (uint32_t)((row * 8 + (ch ^ (row & 7))) * 16);
                uint32_t r0, r1, r2, r3;
                ldsm_x4(r0, r1, r2, r3, bhB + off);
                bh[np*2][0] = r0; bh[np*2][1] = r1; bh[np*2+1][0] = r2; bh[np*2+1][1] = r3;
                ldsm_x4(r0, r1, r2, r3, blB + off);
                bl[np*2][0] = r0; bl[np*2][1] = r1; bl[np*2+1][0] = r2; bl[np*2+1][1] = r3;
            }
            #pragma unroll
            for (int mt = 0; mt < 2; mt++)
                #pragma unroll
                for (int nt = 0; nt < 8; nt++) {
                    mma_bf16(acc[mt][nt], ah[mt], bh[nt]);
                    mma_bf16(acc[mt][nt], ah[mt], bl[nt]);
                    mma_bf16(acc[mt][nt], al[mt], bh[nt]);
                }
        }
        __syncthreads();
    }

    // ---------------- epilogue ----------------
    const int g = lane >> 2, t = lane & 3;
    #pragma unroll
    for (int mt = 0; mt < 2; mt++) {
        #pragma unroll
        for (int half = 0; half < 2; half++) {
            const int m = bm + wm * 32 + mt * 16 + g + half * 8;
            if (m >= M) continue;
            int bI = 0, sI = 0;
            if (MODE == 2) { bI = m / SEQ; sI = m - bI * SEQ; }
            #pragma unroll
            for (int nt = 0; nt < 8; nt++) {
                const int n = bn + wn * 64 + nt * 8 + t * 2;
                float v0 = acc[mt][nt][half * 2 + 0];
                float v1 = acc[mt][nt][half * 2 + 1];
                if (bias) {
                    float2 b2 = *reinterpret_cast<const float2*>(bias + n);
                    v0 += b2.x; v1 += b2.y;
                }
                if (MODE == 2) {
                    const int hd = n >> 6, dd = n & 63;
                    float2 ov = make_float2(v0 * scale, v1 * scale);
                    *reinterpret_cast<float2*>(out +
                        (((size_t)bI * NHEAD + hd) * SEQ + sI) * HDIM + dd) = ov;
                } else if (MODE == 1) {
                    v0 = gelu_exact(v0); v1 = gelu_exact(v1);
                    __nv_bfloat16 h0, h1, l0, l1;
                    split2(v0, h0, l0); split2(v1, h1, l1);
                    const size_t idx = (size_t)m * N + n;
                    *reinterpret_cast<__nv_bfloat162*>(Oh + idx) = __nv_bfloat162(h0, h1);
                    *reinterpret_cast<__nv_bfloat162*>(Ol + idx) = __nv_bfloat162(l0, l1);
                } else {
                    const size_t idx = (size_t)m * N + n;
                    if (res) {
                        float2 r2 = *reinterpret_cast<const float2*>(res + idx);
                        v0 += r2.x; v1 += r2.y;
                    }
                    *reinterpret_cast<float2*>(out + idx) = make_float2(v0, v1);
                    if (SPLIT) {
                        __nv_bfloat16 h0, h1, l0, l1;
                        split2(v0, h0, l0); split2(v1, h1, l1);
                        *reinterpret_cast<__nv_bfloat162*>(Oh + idx) = __nv_bfloat162(h0, h1);
                        *reinterpret_cast<__nv_bfloat162*>(Ol + idx) = __nv_bfloat162(l0, l1);
                    }
                }
            }
        }
    }
}

// ---------------- attention: one thread per q row, flash-style ----------------
__global__ __launch_bounds__(128) void attn_kernel(const float* __restrict__ Q,
                                                   const float* __restrict__ Kp,
                                                   const float* __restrict__ V,
                                                   __nv_bfloat16* __restrict__ Oh,
                                                   __nv_bfloat16* __restrict__ Ol) {
    __shared__ float ks[32 * 64];
    __shared__ float vs[32 * 64];

    const int b = blockIdx.z, h = blockIdx.y;
    const int qrow = blockIdx.x * 128 + threadIdx.x;
    const size_t base = (size_t)(b * NHEAD + h) * SEQ * HDIM;
    const bool valid = qrow < SEQ;

    float q[64], o[64];
    #pragma unroll
    for (int d = 0; d < 64; d++) o[d] = 0.f;
    if (valid) {
        #pragma unroll
        for (int d4 = 0; d4 < 16; d4++) {
            float4 t = *reinterpret_cast<const float4*>(Q + base + (size_t)qrow * 64 + d4 * 4);
            q[d4*4+0] = t.x; q[d4*4+1] = t.y; q[d4*4+2] = t.z; q[d4*4+3] = t.w;
        }
    } else {
        #pragma unroll
        for (int d = 0; d < 64; d++) q[d] = 0.f;
    }

    float mmax = -1e30f, l = 0.f;
    const int ntiles = (SEQ + 31) / 32;

    for (int t = 0; t < ntiles; t++) {
        const int j0 = t * 32;
        #pragma unroll
        for (int r = 0; r < 4; r++) {
            const int fi = r * 512 + threadIdx.x * 4;
            const int jj = fi >> 6;
            float4 kv, vv;
            if (j0 + jj < SEQ) {
                kv = *reinterpret_cast<const float4*>(Kp + base + (size_t)j0 * 64 + fi);
                vv = *reinterpret_cast<const float4*>(V  + base + (size_t)j0 * 64 + fi);
            } else {
                kv = make_float4(0.f, 0.f, 0.f, 0.f);
                vv = kv;
            }
            *reinterpret_cast<float4*>(&ks[fi]) = kv;
            *reinterpret_cast<float4*>(&vs[fi]) = vv;
        }
        __syncthreads();

        float sc[32];
        float tmax = -1e30f;
        #pragma unroll
        for (int jj = 0; jj < 32; jj++) {
            float s = 0.f;
            #pragma unroll
            for (int d4 = 0; d4 < 16; d4++) {
                float4 kv = *reinterpret_cast<const float4*>(&ks[jj * 64 + d4 * 4]);
                s += q[d4*4+0]*kv.x + q[d4*4+1]*kv.y + q[d4*4+2]*kv.z + q[d4*4+3]*kv.w;
            }
            if (j0 + jj >= SEQ) s = -1e30f;
            sc[jj] = s;
            tmax = fmaxf(tmax, s);
        }
        const float nm = fmaxf(mmax, tmax);
        const float corr = __expf(mmax - nm);
        l *= corr;
        #pragma unroll
        for (int d = 0; d < 64; d++) o[d] *= corr;
        #pragma unroll
        for (int jj = 0; jj < 32; jj++) {
            const float p = __expf(sc[jj] - nm);
            l += p;
            #pragma unroll
            for (int d4 = 0; d4 < 16; d4++) {
                float4 vv = *reinterpret_cast<const float4*>(&vs[jj * 64 + d4 * 4]);
                o[d4*4+0] += p * vv.x; o[d4*4+1] += p * vv.y;
                o[d4*4+2] += p * vv.z; o[d4*4+3] += p * vv.w;
            }
        }
        mmax = nm;
        __syncthreads();
    }

    if (valid) {
        const float inv = 1.0f / l;
        const size_t ob = ((size_t)(b * SEQ + qrow)) * CDIM + h * HDIM;
        #pragma unroll
        for (int d4 = 0; d4 < 16; d4++) {
            float v0 = o[d4*4+0]*inv, v1 = o[d4*4+1]*inv;
            float v2 = o[d4*4+2]*inv, v3 = o[d4*4+3]*inv;
            __nv_bfloat16 h0,h1,h2,h3,l0,l1,l2,l3;
            split2(v0,h0,l0); split2(v1,h1,l1);
            split2(v2,h2,l2); split2(v3,h3,l3);
            __nv_bfloat162* hp = reinterpret_cast<__nv_bfloat162*>(Oh + ob + d4 * 4);
            __nv_bfloat162* lp = reinterpret_cast<__nv_bfloat162*>(Ol + ob + d4 * 4);
            hp[0] = __nv_bfloat162(h0, h1); hp[1] = __nv_bfloat162(h2, h3);
            lp[0] = __nv_bfloat162(l0, l1); lp[1] = __nv_bfloat162(l2, l3);
        }
    }
}

// ---------------- launch ----------------
extern "C" void kernel_launch(void* const* d_in, const int* in_sizes, int n_in,
                              void* d_out, int out_size) {
    const float* x     = (const float*)d_in[0];
    const float* Wq    = (const float*)d_in[1];
    const float* bq    = (const float*)d_in[2];
    const float* Wk    = (const float*)d_in[3];
    const float* Wv    = (const float*)d_in[4];
    const float* bv    = (const float*)d_in[5];
    const float* Wo    = (const float*)d_in[6];
    const float* bo    = (const float*)d_in[7];
    const float* ln_aw = (const float*)d_in[8];
    const float* ln_ab = (const float*)d_in[9];
    const float* W1    = (const float*)d_in[10];
    const float* b1    = (const float*)d_in[11];
    const float* W2    = (const float*)d_in[12];
    const float* b2    = (const float*)d_in[13];
    const float* ln_mw = (const float*)d_in[14];
    const float* ln_mb = (const float*)d_in[15];
    const float* Wds   = (const float*)d_in[16];
    const float* bds   = (const float*)d_in[17];
    const float* Wus   = (const float*)d_in[18];
    const float* bus   = (const float*)d_in[19];
    float* out = (float*)d_out;

    float *q, *k, *v, *x1;
    __nv_bfloat16 *Hh, *Hl, *Fh, *Fl, *Dh, *Dl, *Wh, *Wl;
    cudaGetSymbolAddress((void**)&q,  g_q);
    cudaGetSymbolAddress((void**)&k,  g_k);
    cudaGetSymbolAddress((void**)&v,  g_v);
    cudaGetSymbolAddress((void**)&x1, g_x1);
    cudaGetSymbolAddress((void**)&Hh, g_Hh);
    cudaGetSymbolAddress((void**)&Hl, g_Hl);
    cudaGetSymbolAddress((void**)&Fh, g_Fh);
    cudaGetSymbolAddress((void**)&Fl, g_Fl);
    cudaGetSymbolAddress((void**)&Dh, g_Dh);
    cudaGetSymbolAddress((void**)&Dl, g_Dl);
    cudaGetSymbolAddress((void**)&Wh, g_Wh);
    cudaGetSymbolAddress((void**)&Wl, g_Wl);

    cudaFuncSetAttribute(gemm_mma<0, false>, cudaFuncAttributeMaxDynamicSharedMemorySize, GEMM_SMEM);
    cudaFuncSetAttribute(gemm_mma<0, true>,  cudaFuncAttributeMaxDynamicSharedMemorySize, GEMM_SMEM);
    cudaFuncSetAttribute(gemm_mma<1, true>,  cudaFuncAttributeMaxDynamicSharedMemorySize, GEMM_SMEM);
    cudaFuncSetAttribute(gemm_mma<2, false>, cudaFuncAttributeMaxDynamicSharedMemorySize, GEMM_SMEM);

    // split weights
    auto splitw = [&](const float* src, int off, int n) {
        split_kernel<<<(n / 4 + 255) / 256, 256>>>(src, Wh + off, Wl + off, n / 4);
    };
    splitw(Wq,  OFF_WQ,  CC);
    splitw(Wk,  OFF_WK,  CC);
    splitw(Wv,  OFF_WV,  CC);
    splitw(Wo,  OFF_WO,  CC);
    splitw(W1,  OFF_W1,  W1SZ);
    splitw(W2,  OFF_W2,  W1SZ);
    splitw(Wds, OFF_WDS, ASZ);
    splitw(Wus, OFF_WUS, ASZ);

    const int mg = (MROWS + 127) / 128;
    dim3 gC(CDIM / 128, mg);
    dim3 gF(FDIM / 128, mg);
    dim3 gA(ADIM / 128, mg);
    dim3 gAt((SEQ + 127) / 128, NHEAD, BATCH);

    // ---- attention ----
    ln_split_kernel<<<MROWS, 256>>>(x, ln_aw, ln_ab, Hh, Hl);
    gemm_mma<2, false><<<gC, 256, GEMM_SMEM>>>(Hh, Hl, Wh + OFF_WQ, Wl + OFF_WQ,
        bq, nullptr, q, nullptr, nullptr, MROWS, CDIM, CDIM, QKSCALE);
    gemm_mma<2, false><<<gC, 256, GEMM_SMEM>>>(Hh, Hl, Wh + OFF_WK, Wl + OFF_WK,
        nullptr, nullptr, k, nullptr, nullptr, MROWS, CDIM, CDIM, QKSCALE);
    gemm_mma<2, false><<<gC, 256, GEMM_SMEM>>>(Hh, Hl, Wh + OFF_WV, Wl + OFF_WV,
        bv, nullptr, v, nullptr, nullptr, MROWS, CDIM, CDIM, 1.0f);
    attn_kernel<<<gAt, 128>>>(q, k, v, Hh, Hl);
    gemm_mma<0, false><<<gC, 256, GEMM_SMEM>>>(Hh, Hl, Wh + OFF_WO, Wl + OFF_WO,
        bo, x, x1, nullptr, nullptr, MROWS, CDIM, CDIM, 1.0f);

    // ---- MLP ----
    ln_split_kernel<<<MROWS, 256>>>(x1, ln_mw, ln_mb, Hh, Hl);
    gemm_mma<1, true><<<gF, 256, GEMM_SMEM>>>(Hh, Hl, Wh + OFF_W1, Wl + OFF_W1,
        b1, nullptr, nullptr, Fh, Fl, MROWS, FDIM, CDIM, 1.0f);
    gemm_mma<0, true><<<gC, 256, GEMM_SMEM>>>(Fh, Fl, Wh + OFF_W2, Wl + OFF_W2,
        b2, x1, out, Hh, Hl, MROWS, CDIM, FDIM, 1.0f);

    // ---- bottleneck adapter ----
    gemm_mma<1, true><<<gA, 256, GEMM_SMEM>>>(Hh, Hl, Wh + OFF_WDS, Wl + OFF_WDS,
        bds, nullptr, nullptr, Dh, Dl, MROWS, ADIM, CDIM, 1.0f);
    gemm_mma<0, false><<<gC, 256, GEMM_SMEM>>>(Dh, Dl, Wh + OFF_WUS, Wl + OFF_WUS,
        bus, out, out, nullptr, nullptr, MROWS, CDIM, ADIM, 1.0f);
}

// round 4
// speedup vs baseline: 2.0116x; 1.3456x over previous
#include <cuda_runtime.h>
#include <cuda_bf16.h>
#include <math.h>
#include <stdint.h>

// ---------------- problem constants ----------------
#define BATCH   4
#define SEQ     1500
#define CDIM    1024
#define NHEAD   16
#define HDIM    64
#define FDIM    4096
#define ADIM    256
#define MROWS   (BATCH * SEQ)          // 6000
#define QKSCALE 0.35355339059327379f   // 64^-0.25
#define LOG2E   1.4426950408889634f

// ---------------- scratch ----------------
__device__ float g_x1[MROWS * CDIM];

// split-bf16 QKV in [B,H,S,D]
__device__ __nv_bfloat16 g_qh[MROWS * CDIM];
__device__ __nv_bfloat16 g_ql[MROWS * CDIM];
__device__ __nv_bfloat16 g_kh[MROWS * CDIM];
__device__ __nv_bfloat16 g_kl[MROWS * CDIM];
__device__ __nv_bfloat16 g_vh[MROWS * CDIM];
__device__ __nv_bfloat16 g_vl[MROWS * CDIM];

__device__ __nv_bfloat16 g_Hh[MROWS * CDIM];
__device__ __nv_bfloat16 g_Hl[MROWS * CDIM];
__device__ __nv_bfloat16 g_Fh[MROWS * FDIM];
__device__ __nv_bfloat16 g_Fl[MROWS * FDIM];
__device__ __nv_bfloat16 g_Dh[MROWS * ADIM];
__device__ __nv_bfloat16 g_Dl[MROWS * ADIM];

#define CC      (CDIM * CDIM)
#define W1SZ    (FDIM * CDIM)
#define ASZ     (ADIM * CDIM)
#define OFF_WQ  0
#define OFF_WK  (CC)
#define OFF_WV  (2 * CC)
#define OFF_WO  (3 * CC)
#define OFF_W1  (4 * CC)
#define OFF_W2  (4 * CC + W1SZ)
#define OFF_WDS (4 * CC + 2 * W1SZ)
#define OFF_WUS (4 * CC + 2 * W1SZ + ASZ)
#define WTOT    (4 * CC + 2 * W1SZ + 2 * ASZ)
__device__ __nv_bfloat16 g_Wh[WTOT];
__device__ __nv_bfloat16 g_Wl[WTOT];

// ---------------- helpers ----------------
__device__ __forceinline__ float gelu_exact(float v) {
    return 0.5f * v * (1.0f + erff(v * 0.70710678118654752f));
}
__device__ __forceinline__ void split2(float x, __nv_bfloat16& h, __nv_bfloat16& l) {
    h = __float2bfloat16(x);
    l = __float2bfloat16(x - __bfloat162float(h));
}
__device__ __forceinline__ uint32_t smem_u32(const void* p) {
    uint32_t a;
    asm("{ .reg .u64 t; cvta.to.shared.u64 t, %1; cvt.u32.u64 %0, t; }" : "=r"(a) : "l"(p));
    return a;
}
__device__ __forceinline__ void cp_async16(uint32_t dst, const void* src) {
    asm volatile("cp.async.cg.shared.global [%0], [%1], 16;" :: "r"(dst), "l"(src));
}
__device__ __forceinline__ void ldsm_x4(uint32_t& r0, uint32_t& r1, uint32_t& r2,
                                        uint32_t& r3, uint32_t addr) {
    asm volatile("ldmatrix.sync.aligned.m8n8.x4.shared.b16 {%0,%1,%2,%3}, [%4];"
        : "=r"(r0), "=r"(r1), "=r"(r2), "=r"(r3) : "r"(addr));
}
__device__ __forceinline__ void ldsm_x4t(uint32_t& r0, uint32_t& r1, uint32_t& r2,
                                         uint32_t& r3, uint32_t addr) {
    asm volatile("ldmatrix.sync.aligned.m8n8.x4.trans.shared.b16 {%0,%1,%2,%3}, [%4];"
        : "=r"(r0), "=r"(r1), "=r"(r2), "=r"(r3) : "r"(addr));
}
__device__ __forceinline__ void mma_bf16(float* c, const uint32_t* a, const uint32_t* b) {
    asm volatile("mma.sync.aligned.m16n8k16.row.col.f32.bf16.bf16.f32 "
        "{%0,%1,%2,%3}, {%4,%5,%6,%7}, {%8,%9}, {%0,%1,%2,%3};"
        : "+f"(c[0]), "+f"(c[1]), "+f"(c[2]), "+f"(c[3])
        : "r"(a[0]), "r"(a[1]), "r"(a[2]), "r"(a[3]), "r"(b[0]), "r"(b[1]));
}
__device__ __forceinline__ void split_pack(float f0, float f1, uint32_t& ph, uint32_t& pl) {
    __nv_bfloat16 h0, l0, h1, l1;
    split2(f0, h0, l0); split2(f1, h1, l1);
    ph = (uint32_t)__bfloat16_as_ushort(h0) | ((uint32_t)__bfloat16_as_ushort(h1) << 16);
    pl = (uint32_t)__bfloat16_as_ushort(l0) | ((uint32_t)__bfloat16_as_ushort(l1) << 16);
}
#define SWZOFF(row, ch) ((uint32_t)((((row) * 8) + ((ch) ^ ((row) & 7))) * 16))

// ---------------- split kernels ----------------
__global__ __launch_bounds__(256) void split_kernel(const float* __restrict__ s,
                                                    __nv_bfloat16* __restrict__ h,
                                                    __nv_bfloat16* __restrict__ l,
                                                    int n4) {
    int i = blockIdx.x * 256 + threadIdx.x;
    if (i >= n4) return;
    float4 v = reinterpret_cast<const float4*>(s)[i];
    __nv_bfloat16 h0, h1, h2, h3, l0, l1, l2, l3;
    split2(v.x, h0, l0); split2(v.y, h1, l1);
    split2(v.z, h2, l2); split2(v.w, h3, l3);
    __nv_bfloat162* hp = reinterpret_cast<__nv_bfloat162*>(h + (size_t)i * 4);
    __nv_bfloat162* lp = reinterpret_cast<__nv_bfloat162*>(l + (size_t)i * 4);
    hp[0] = __nv_bfloat162(h0, h1); hp[1] = __nv_bfloat162(h2, h3);
    lp[0] = __nv_bfloat162(l0, l1); lp[1] = __nv_bfloat162(l2, l3);
}

__global__ __launch_bounds__(256) void ln_split_kernel(const float* __restrict__ x,
                                                       const float* __restrict__ w,
                                                       const float* __restrict__ b,
                                                       __nv_bfloat16* __restrict__ oh,
                                                       __nv_bfloat16* __restrict__ ol) {
    __shared__ float red[2][8];
    const int row = blockIdx.x;
    const int tid = threadIdx.x;
    const int lane = tid & 31, wid = tid >> 5;

    float4 v = reinterpret_cast<const float4*>(x + (size_t)row * CDIM)[tid];
    float s  = v.x + v.y + v.z + v.w;
    float ss = v.x*v.x + v.y*v.y + v.z*v.z + v.w*v.w;
    #pragma unroll
    for (int o = 16; o; o >>= 1) {
        s  += __shfl_xor_sync(0xffffffffu, s,  o);
        ss += __shfl_xor_sync(0xffffffffu, ss, o);
    }
    if (lane == 0) { red[0][wid] = s; red[1][wid] = ss; }
    __syncthreads();
    float fs = 0.f, fss = 0.f;
    #pragma unroll
    for (int i = 0; i < 8; i++) { fs += red[0][i]; fss += red[1][i]; }
    const float mu  = fs * (1.0f / CDIM);
    const float var = fss * (1.0f / CDIM) - mu * mu;
    const float r   = rsqrtf(var + 1e-5f);

    float4 wv = reinterpret_cast<const float4*>(w)[tid];
    float4 bv = reinterpret_cast<const float4*>(b)[tid];
    float o0 = (v.x - mu) * r * wv.x + bv.x;
    float o1 = (v.y - mu) * r * wv.y + bv.y;
    float o2 = (v.z - mu) * r * wv.z + bv.z;
    float o3 = (v.w - mu) * r * wv.w + bv.w;
    __nv_bfloat16 h0,h1,h2,h3,l0,l1,l2,l3;
    split2(o0,h0,l0); split2(o1,h1,l1); split2(o2,h2,l2); split2(o3,h3,l3);
    size_t base = (size_t)row * CDIM + tid * 4;
    __nv_bfloat162* hp = reinterpret_cast<__nv_bfloat162*>(oh + base);
    __nv_bfloat162* lp = reinterpret_cast<__nv_bfloat162*>(ol + base);
    hp[0] = __nv_bfloat162(h0, h1); hp[1] = __nv_bfloat162(h2, h3);
    lp[0] = __nv_bfloat162(l0, l1); lp[1] = __nv_bfloat162(l2, l3);
}

// ---------------- split-bf16 tensor-core GEMM (mma.sync) ----------------
// MODE 0: v = acc+bias(+res) -> fp32 out (optional SPLIT bf16 out)
// MODE 1: v = gelu(acc+bias) -> split bf16 out
// MODE 2: v = (acc+bias)*scale -> split bf16 out transposed to [B,H,S,D] (Oh/Ol)
#define BK 64
#define TILEB  (128 * BK * 2)
#define STAGEB (4 * TILEB)
#define GEMM_SMEM (2 * STAGEB)

template<int MODE, bool SPLIT>
__global__ __launch_bounds__(256, 1) void gemm_mma(
        const __nv_bfloat16* __restrict__ Ah, const __nv_bfloat16* __restrict__ Al,
        const __nv_bfloat16* __restrict__ Bh, const __nv_bfloat16* __restrict__ Bl,
        const float* __restrict__ bias, const float* __restrict__ res,
        float* __restrict__ out,
        __nv_bfloat16* __restrict__ Oh, __nv_bfloat16* __restrict__ Ol,
        int M, int N, int K, float scale) {
    extern __shared__ char smem[];
    const uint32_t sbase = smem_u32(smem);
    const int tid  = threadIdx.x;
    const int warp = tid >> 5, lane = tid & 31;
    const int bm = blockIdx.y * 128, bn = blockIdx.x * 128;
    const int wm = warp & 3, wn = warp >> 2;

    const int ltile = tid >> 6;
    const int lrow0 = (tid & 63) * 2;
    const __nv_bfloat16* lsrc = (ltile == 0) ? Ah : (ltile == 1) ? Al
                              : (ltile == 2) ? Bh : Bl;
    const bool isA = (ltile < 2);
    int gr0 = isA ? (bm + lrow0) : (bn + lrow0);
    int gr1 = gr0 + 1;
    if (isA) { gr0 = min(gr0, M - 1); gr1 = min(gr1, M - 1); }
    const __nv_bfloat16* src0 = lsrc + (size_t)gr0 * K;
    const __nv_bfloat16* src1 = lsrc + (size_t)gr1 * K;
    const uint32_t dtile = sbase + ltile * TILEB;
    uint32_t d0[8], d1[8];
    #pragma unroll
    for (int c = 0; c < 8; c++) {
        d0[c] = SWZOFF(lrow0, c);
        d1[c] = SWZOFF(lrow0 + 1, c);
    }

    float acc[2][8][4];
    #pragma unroll
    for (int a = 0; a < 2; a++)
        #pragma unroll
        for (int b = 0; b < 8; b++)
            #pragma unroll
            for (int c = 0; c < 4; c++) acc[a][b][c] = 0.f;

    const int nch = K / BK;

    {
        const uint32_t db = dtile;
        #pragma unroll
        for (int c = 0; c < 8; c++) {
            cp_async16(db + d0[c], src0 + c * 8);
            cp_async16(db + d1[c], src1 + c * 8);
        }
        asm volatile("cp.async.commit_group;");
    }

    const int arow = (lane & 15);
    const int acsel = lane >> 4;
    const int brow = (lane & 7) + ((lane >> 4) & 1) * 8;
    const int bcsel = (lane >> 3) & 1;

    for (int kc = 0; kc < nch; kc++) {
        const int st = kc & 1;
        if (kc + 1 < nch) {
            const uint32_t db = dtile + (st ^ 1) * STAGEB;
            const int k0 = (kc + 1) * BK;
            #pragma unroll
            for (int c = 0; c < 8; c++) {
                cp_async16(db + d0[c], src0 + k0 + c * 8);
                cp_async16(db + d1[c], src1 + k0 + c * 8);
            }
            asm volatile("cp.async.commit_group;");
            asm volatile("cp.async.wait_group 1;");
        } else {
            asm volatile("cp.async.wait_group 0;");
        }
        __syncthreads();

        const uint32_t base = sbase + st * STAGEB;
        const uint32_t ahB = base, alB = base + TILEB;
        const uint32_t bhB = base + 2 * TILEB, blB = base + 3 * TILEB;

        #pragma unroll
        for (int ks = 0; ks < 4; ks++) {
            uint32_t ah[2][4], al[2][4], bh[8][2], bl[8][2];
            #pragma unroll
            for (int mt = 0; mt < 2; mt++) {
                const int row = wm * 32 + mt * 16 + arow;
                const int ch  = ks * 2 + acsel;
                const uint32_t off = SWZOFF(row, ch);
                ldsm_x4(ah[mt][0], ah[mt][1], ah[mt][2], ah[mt][3], ahB + off);
                ldsm_x4(al[mt][0], al[mt][1], al[mt][2], al[mt][3], alB + off);
            }
            #pragma unroll
            for (int np = 0; np < 4; np++) {
                const int row = wn * 64 + np * 16 + brow;
                const int ch  = ks * 2 + bcsel;
                const uint32_t off = SWZOFF(row, ch);
                uint32_t r0, r1, r2, r3;
                ldsm_x4(r0, r1, r2, r3, bhB + off);
                bh[np*2][0] = r0; bh[np*2][1] = r1; bh[np*2+1][0] = r2; bh[np*2+1][1] = r3;
                ldsm_x4(r0, r1, r2, r3, blB + off);
                bl[np*2][0] = r0; bl[np*2][1] = r1; bl[np*2+1][0] = r2; bl[np*2+1][1] = r3;
            }
            #pragma unroll
            for (int mt = 0; mt < 2; mt++)
                #pragma unroll
                for (int nt = 0; nt < 8; nt++) {
                    mma_bf16(acc[mt][nt], ah[mt], bh[nt]);
                    mma_bf16(acc[mt][nt], ah[mt], bl[nt]);
                    mma_bf16(acc[mt][nt], al[mt], bh[nt]);
                }
        }
        __syncthreads();
    }

    const int g = lane >> 2, t = lane & 3;
    #pragma unroll
    for (int mt = 0; mt < 2; mt++) {
        #pragma unroll
        for (int half = 0; half < 2; half++) {
            const int m = bm + wm * 32 + mt * 16 + g + half * 8;
            if (m >= M) continue;
            int bI = 0, sI = 0;
            if (MODE == 2) { bI = m / SEQ; sI = m - bI * SEQ; }
            #pragma unroll
            for (int nt = 0; nt < 8; nt++) {
                const int n = bn + wn * 64 + nt * 8 + t * 2;
                float v0 = acc[mt][nt][half * 2 + 0];
                float v1 = acc[mt][nt][half * 2 + 1];
                if (bias) {
                    float2 b2 = *reinterpret_cast<const float2*>(bias + n);
                    v0 += b2.x; v1 += b2.y;
                }
                if (MODE == 2) {
                    v0 *= scale; v1 *= scale;
                    __nv_bfloat16 h0, h1, l0, l1;
                    split2(v0, h0, l0); split2(v1, h1, l1);
                    const int hd = n >> 6, dd = n & 63;
                    const size_t idx = (((size_t)bI * NHEAD + hd) * SEQ + sI) * HDIM + dd;
                    *reinterpret_cast<__nv_bfloat162*>(Oh + idx) = __nv_bfloat162(h0, h1);
                    *reinterpret_cast<__nv_bfloat162*>(Ol + idx) = __nv_bfloat162(l0, l1);
                } else if (MODE == 1) {
                    v0 = gelu_exact(v0); v1 = gelu_exact(v1);
                    __nv_bfloat16 h0, h1, l0, l1;
                    split2(v0, h0, l0); split2(v1, h1, l1);
                    const size_t idx = (size_t)m * N + n;
                    *reinterpret_cast<__nv_bfloat162*>(Oh + idx) = __nv_bfloat162(h0, h1);
                    *reinterpret_cast<__nv_bfloat162*>(Ol + idx) = __nv_bfloat162(l0, l1);
                } else {
                    const size_t idx = (size_t)m * N + n;
                    if (res) {
                        float2 r2 = *reinterpret_cast<const float2*>(res + idx);
                        v0 += r2.x; v1 += r2.y;
                    }
                    *reinterpret_cast<float2*>(out + idx) = make_float2(v0, v1);
                    if (SPLIT) {
                        __nv_bfloat16 h0, h1, l0, l1;
                        split2(v0, h0, l0); split2(v1, h1, l1);
                        *reinterpret_cast<__nv_bfloat162*>(Oh + idx) = __nv_bfloat162(h0, h1);
                        *reinterpret_cast<__nv_bfloat162*>(Ol + idx) = __nv_bfloat162(l0, l1);
                    }
                }
            }
        }
    }
}

// ---------------- tensor-core flash attention ----------------
// Q/K/V split-bf16 in [B,H,S,D]; O split-bf16 [token][C].
// CTA: 128 q rows, 8 warps (m16 each); key tiles of 64, double-buffered cp.async.
#define ATQ 128
#define ATK 64
#define QTILE_B (ATQ * 128)            // 16384 per array
#define KTILE_B (ATK * 128)            // 8192 per array
#define AT_ST0  (2 * QTILE_B)          // 32768
#define AT_STAGE (4 * KTILE_B)         // 32768
#define ATT_SMEM (2 * QTILE_B + 2 * AT_STAGE)   // 98304

__global__ __launch_bounds__(256, 1) void attn_mma(
        const __nv_bfloat16* __restrict__ Qh, const __nv_bfloat16* __restrict__ Ql,
        const __nv_bfloat16* __restrict__ Kh, const __nv_bfloat16* __restrict__ Kl,
        const __nv_bfloat16* __restrict__ Vh, const __nv_bfloat16* __restrict__ Vl,
        __nv_bfloat16* __restrict__ Oh, __nv_bfloat16* __restrict__ Ol) {
    extern __shared__ char smem[];
    const uint32_t sbase = smem_u32(smem);
    const int tid = threadIdx.x;
    const int warp = tid >> 5, lane = tid & 31;
    const int b = blockIdx.z, h = blockIdx.y;
    const int q0 = blockIdx.x * ATQ;
    const size_t hb = (size_t)(b * NHEAD + h) * SEQ;
    const int ntiles = (SEQ + ATK - 1) / ATK;   // 24

    // ---- Q tile load (group 0, together with KV stage 0) ----
    {
        const __nv_bfloat16* src = (tid >= 128) ? Ql : Qh;
        const int row = tid & 127;
        const int qr = min(q0 + row, SEQ - 1);
        const __nv_bfloat16* sp = src + (hb + qr) * HDIM;
        const uint32_t db = sbase + ((tid >= 128) ? QTILE_B : 0);
        #pragma unroll
        for (int c = 0; c < 8; c++) cp_async16(db + SWZOFF(row, c), sp + c * 8);
    }
    // KV loader: array = tid>>6 (Kh,Kl,Vh,Vl), row = tid&63
    const int kva = tid >> 6;
    const int kvr = tid & 63;
    const __nv_bfloat16* kvsrc = (kva == 0) ? Kh : (kva == 1) ? Kl : (kva == 2) ? Vh : Vl;
    const uint32_t kvdst = sbase + AT_ST0 + kva * KTILE_B;
    #define LOADKV(tt, st) do { \
        const int kr_ = min((tt) * ATK + kvr, SEQ - 1); \
        const __nv_bfloat16* sp_ = kvsrc + (hb + kr_) * HDIM; \
        const uint32_t db_ = kvdst + (st) * AT_STAGE; \
        _Pragma("unroll") \
        for (int c_ = 0; c_ < 8; c_++) cp_async16(db_ + SWZOFF(kvr, c_), sp_ + c_ * 8); \
        asm volatile("cp.async.commit_group;"); \
    } while (0)

    LOADKV(0, 0);
    LOADKV(1, 1);

    float o[8][4];
    #pragma unroll
    for (int i = 0; i < 8; i++)
        #pragma unroll
        for (int j = 0; j < 4; j++) o[i][j] = 0.f;
    float m0 = -1e30f, m1 = -1e30f, l0 = 0.f, l1 = 0.f;
    uint32_t qfh[4][4], qfl[4][4];
    const int gq = lane >> 2, tq = lane & 3;

    for (int t = 0; t < ntiles; t++) {
        if (t + 1 < ntiles) asm volatile("cp.async.wait_group 1;");
        else                asm volatile("cp.async.wait_group 0;");
        __syncthreads();

        if (t == 0) {
            #pragma unroll
            for (int ks = 0; ks < 4; ks++) {
                const int row = warp * 16 + (lane & 15);
                const int ch  = ks * 2 + (lane >> 4);
                const uint32_t off = SWZOFF(row, ch);
                ldsm_x4(qfh[ks][0], qfh[ks][1], qfh[ks][2], qfh[ks][3], sbase + off);
                ldsm_x4(qfl[ks][0], qfl[ks][1], qfl[ks][2], qfl[ks][3], sbase + QTILE_B + off);
            }
        }

        const uint32_t kb = sbase + AT_ST0 + (t & 1) * AT_STAGE;

        // ---- S = Q K^T ----
        float c[8][4];
        #pragma unroll
        for (int i = 0; i < 8; i++)
            #pragma unroll
            for (int j = 0; j < 4; j++) c[i][j] = 0.f;

        #pragma unroll
        for (int ks = 0; ks < 4; ks++) {
            uint32_t bh[8][2], bl[8][2];
            #pragma unroll
            for (int np = 0; np < 4; np++) {
                const int row = np * 16 + (lane & 7) + ((lane >> 4) & 1) * 8;
                const int ch  = ks * 2 + ((lane >> 3) & 1);
                const uint32_t off = SWZOFF(row, ch);
                uint32_t r0, r1, r2, r3;
                ldsm_x4(r0, r1, r2, r3, kb + off);
                bh[np*2][0] = r0; bh[np*2][1] = r1; bh[np*2+1][0] = r2; bh[np*2+1][1] = r3;
                ldsm_x4(r0, r1, r2, r3, kb + KTILE_B + off);
                bl[np*2][0] = r0; bl[np*2][1] = r1; bl[np*2+1][0] = r2; bl[np*2+1][1] = r3;
            }
            #pragma unroll
            for (int nt = 0; nt < 8; nt++) {
                mma_bf16(c[nt], qfh[ks], bh[nt]);
                mma_bf16(c[nt], qfh[ks], bl[nt]);
                mma_bf16(c[nt], qfl[ks], bh[nt]);
            }
        }

        // ---- online softmax ----
        float tmax0 = -1e30f, tmax1 = -1e30f;
        #pragma unroll
        for (int nt = 0; nt < 8; nt++) {
            tmax0 = fmaxf(tmax0, fmaxf(c[nt][0], c[nt][1]));
            tmax1 = fmaxf(tmax1, fmaxf(c[nt][2], c[nt][3]));
        }
        tmax0 = fmaxf(tmax0, __shfl_xor_sync(0xffffffffu, tmax0, 1));
        tmax0 = fmaxf(tmax0, __shfl_xor_sync(0xffffffffu, tmax0, 2));
        tmax1 = fmaxf(tmax1, __shfl_xor_sync(0xffffffffu, tmax1, 1));
        tmax1 = fmaxf(tmax1, __shfl_xor_sync(0xffffffffu, tmax1, 2));
        const float nm0 = fmaxf(m0, tmax0), nm1 = fmaxf(m1, tmax1);
        const float corr0 = exp2f((m0 - nm0) * LOG2E);
        const float corr1 = exp2f((m1 - nm1) * LOG2E);
        #pragma unroll
        for (int nt = 0; nt < 8; nt++) {
            o[nt][0] *= corr0; o[nt][1] *= corr0;
            o[nt][2] *= corr1; o[nt][3] *= corr1;
        }
        float rs0 = 0.f, rs1 = 0.f;
        const bool needmask = (t * ATK + ATK > SEQ);
        #pragma unroll
        for (int nt = 0; nt < 8; nt++) {
            float p00 = exp2f((c[nt][0] - nm0) * LOG2E);
            float p01 = exp2f((c[nt][1] - nm0) * LOG2E);
            float p10 = exp2f((c[nt][2] - nm1) * LOG2E);
            float p11 = exp2f((c[nt][3] - nm1) * LOG2E);
            if (needmask) {
                const int jc = t * ATK + nt * 8 + tq * 2;
                if (jc >= SEQ)     { p00 = 0.f; p10 = 0.f; }
                if (jc + 1 >= SEQ) { p01 = 0.f; p11 = 0.f; }
            }
            rs0 += p00 + p01; rs1 += p10 + p11;
            c[nt][0] = p00; c[nt][1] = p01; c[nt][2] = p10; c[nt][3] = p11;
        }
        rs0 += __shfl_xor_sync(0xffffffffu, rs0, 1);
        rs0 += __shfl_xor_sync(0xffffffffu, rs0, 2);
        rs1 += __shfl_xor_sync(0xffffffffu, rs1, 1);
        rs1 += __shfl_xor_sync(0xffffffffu, rs1, 2);
        l0 = l0 * corr0 + rs0;
        l1 = l1 * corr1 + rs1;
        m0 = nm0; m1 = nm1;

        // ---- pack P into split bf16 A fragments ----
        uint32_t pah[4][4], pal[4][4];
        #pragma unroll
        for (int ks = 0; ks < 4; ks++) {
            split_pack(c[2*ks][0],   c[2*ks][1],   pah[ks][0], pal[ks][0]);
            split_pack(c[2*ks][2],   c[2*ks][3],   pah[ks][1], pal[ks][1]);
            split_pack(c[2*ks+1][0], c[2*ks+1][1], pah[ks][2], pal[ks][2]);
            split_pack(c[2*ks+1][2], c[2*ks+1][3], pah[ks][3], pal[ks][3]);
        }

        // ---- O += P V ----
        #pragma unroll
        for (int ks = 0; ks < 4; ks++) {
            uint32_t vh[8][2], vl[8][2];
            #pragma unroll
            for (int np = 0; np < 4; np++) {
                const int row = ks * 16 + (lane & 7) + ((lane >> 3) & 1) * 8;
                const int ch  = np * 2 + (lane >> 4);
                const uint32_t off = SWZOFF(row, ch);
                uint32_t r0, r1, r2, r3;
                ldsm_x4t(r0, r1, r2, r3, kb + 2 * KTILE_B + off);
                vh[np*2][0] = r0; vh[np*2][1] = r1; vh[np*2+1][0] = r2; vh[np*2+1][1] = r3;
                ldsm_x4t(r0, r1, r2, r3, kb + 3 * KTILE_B + off);
                vl[np*2][0] = r0; vl[np*2][1] = r1; vl[np*2+1][0] = r2; vl[np*2+1][1] = r3;
            }
            #pragma unroll
            for (int nt = 0; nt < 8; nt++) {
                mma_bf16(o[nt], pah[ks], vh[nt]);
                mma_bf16(o[nt], pah[ks], vl[nt]);
                mma_bf16(o[nt], pal[ks], vh[nt]);
            }
        }
        __syncthreads();
        if (t + 2 < ntiles) LOADKV(t + 2, t & 1);
    }

    // ---- epilogue ----
    const float inv0 = 1.0f / l0, inv1 = 1.0f / l1;
    const int token0 = q0 + warp * 16 + gq;
    const int token1 = token0 + 8;
    #pragma unroll
    for (int nt = 0; nt < 8; nt++) {
        const int d0 = nt * 8 + tq * 2;
        if (token0 < SEQ) {
            float v0 = o[nt][0] * inv0, v1 = o[nt][1] * inv0;
            __nv_bfloat16 h0, h1, lo0, lo1;
            split2(v0, h0, lo0); split2(v1, h1, lo1);
            const size_t idx = (size_t)(b * SEQ + token0) * CDIM + h * HDIM + d0;
            *reinterpret_cast<__nv_bfloat162*>(Oh + idx) = __nv_bfloat162(h0, h1);
            *reinterpret_cast<__nv_bfloat162*>(Ol + idx) = __nv_bfloat162(lo0, lo1);
        }
        if (token1 < SEQ) {
            float v0 = o[nt][2] * inv1, v1 = o[nt][3] * inv1;
            __nv_bfloat16 h0, h1, lo0, lo1;
            split2(v0, h0, lo0); split2(v1, h1, lo1);
            const size_t idx = (size_t)(b * SEQ + token1) * CDIM + h * HDIM + d0;
            *reinterpret_cast<__nv_bfloat162*>(Oh + idx) = __nv_bfloat162(h0, h1);
            *reinterpret_cast<__nv_bfloat162*>(Ol + idx) = __nv_bfloat162(lo0, lo1);
        }
    }
}

// ---------------- launch ----------------
extern "C" void kernel_launch(void* const* d_in, const int* in_sizes, int n_in,
                              void* d_out, int out_size) {
    const float* x     = (const float*)d_in[0];
    const float* Wq    = (const float*)d_in[1];
    const float* bq    = (const float*)d_in[2];
    const float* Wk    = (const float*)d_in[3];
    const float* Wv    = (const float*)d_in[4];
    const float* bv    = (const float*)d_in[5];
    const float* Wo    = (const float*)d_in[6];
    const float* bo    = (const float*)d_in[7];
    const float* ln_aw = (const float*)d_in[8];
    const float* ln_ab = (const float*)d_in[9];
    const float* W1    = (const float*)d_in[10];
    const float* b1    = (const float*)d_in[11];
    const float* W2    = (const float*)d_in[12];
    const float* b2    = (const float*)d_in[13];
    const float* ln_mw = (const float*)d_in[14];
    const float* ln_mb = (const float*)d_in[15];
    const float* Wds   = (const float*)d_in[16];
    const float* bds   = (const float*)d_in[17];
    const float* Wus   = (const float*)d_in[18];
    const float* bus   = (const float*)d_in[19];
    float* out = (float*)d_out;

    float *x1;
    __nv_bfloat16 *qh, *ql, *kh, *kl, *vh, *vl;
    __nv_bfloat16 *Hh, *Hl, *Fh, *Fl, *Dh, *Dl, *Wh, *Wl;
    cudaGetSymbolAddress((void**)&x1, g_x1);
    cudaGetSymbolAddress((void**)&qh, g_qh);
    cudaGetSymbolAddress((void**)&ql, g_ql);
    cudaGetSymbolAddress((void**)&kh, g_kh);
    cudaGetSymbolAddress((void**)&kl, g_kl);
    cudaGetSymbolAddress((void**)&vh, g_vh);
    cudaGetSymbolAddress((void**)&vl, g_vl);
    cudaGetSymbolAddress((void**)&Hh, g_Hh);
    cudaGetSymbolAddress((void**)&Hl, g_Hl);
    cudaGetSymbolAddress((void**)&Fh, g_Fh);
    cudaGetSymbolAddress((void**)&Fl, g_Fl);
    cudaGetSymbolAddress((void**)&Dh, g_Dh);
    cudaGetSymbolAddress((void**)&Dl, g_Dl);
    cudaGetSymbolAddress((void**)&Wh, g_Wh);
    cudaGetSymbolAddress((void**)&Wl, g_Wl);

    cudaFuncSetAttribute(gemm_mma<0, false>, cudaFuncAttributeMaxDynamicSharedMemorySize, GEMM_SMEM);
    cudaFuncSetAttribute(gemm_mma<0, true>,  cudaFuncAttributeMaxDynamicSharedMemorySize, GEMM_SMEM);
    cudaFuncSetAttribute(gemm_mma<1, true>,  cudaFuncAttributeMaxDynamicSharedMemorySize, GEMM_SMEM);
    cudaFuncSetAttribute(gemm_mma<2, false>, cudaFuncAttributeMaxDynamicSharedMemorySize, GEMM_SMEM);
    cudaFuncSetAttribute(attn_mma, cudaFuncAttributeMaxDynamicSharedMemorySize, ATT_SMEM);

    auto splitw = [&](const float* src, int off, int n) {
        split_kernel<<<(n / 4 + 255) / 256, 256>>>(src, Wh + off, Wl + off, n / 4);
    };
    splitw(Wq,  OFF_WQ,  CC);
    splitw(Wk,  OFF_WK,  CC);
    splitw(Wv,  OFF_WV,  CC);
    splitw(Wo,  OFF_WO,  CC);
    splitw(W1,  OFF_W1,  W1SZ);
    splitw(W2,  OFF_W2,  W1SZ);
    splitw(Wds, OFF_WDS, ASZ);
    splitw(Wus, OFF_WUS, ASZ);

    const int mg = (MROWS + 127) / 128;
    dim3 gC(CDIM / 128, mg);
    dim3 gF(FDIM / 128, mg);
    dim3 gA(ADIM / 128, mg);
    dim3 gAt((SEQ + ATQ - 1) / ATQ, NHEAD, BATCH);   // (12,16,4)

    // ---- attention ----
    ln_split_kernel<<<MROWS, 256>>>(x, ln_aw, ln_ab, Hh, Hl);
    gemm_mma<2, false><<<gC, 256, GEMM_SMEM>>>(Hh, Hl, Wh + OFF_WQ, Wl + OFF_WQ,
        bq, nullptr, nullptr, qh, ql, MROWS, CDIM, CDIM, QKSCALE);
    gemm_mma<2, false><<<gC, 256, GEMM_SMEM>>>(Hh, Hl, Wh + OFF_WK, Wl + OFF_WK,
        nullptr, nullptr, nullptr, kh, kl, MROWS, CDIM, CDIM, QKSCALE);
    gemm_mma<2, false><<<gC, 256, GEMM_SMEM>>>(Hh, Hl, Wh + OFF_WV, Wl + OFF_WV,
        bv, nullptr, nullptr, vh, vl, MROWS, CDIM, CDIM, 1.0f);
    attn_mma<<<gAt, 256, ATT_SMEM>>>(qh, ql, kh, kl, vh, vl, Hh, Hl);
    gemm_mma<0, false><<<gC, 256, GEMM_SMEM>>>(Hh, Hl, Wh + OFF_WO, Wl + OFF_WO,
        bo, x, x1, nullptr, nullptr, MROWS, CDIM, CDIM, 1.0f);

    // ---- MLP ----
    ln_split_kernel<<<MROWS, 256>>>(x1, ln_mw, ln_mb, Hh, Hl);
    gemm_mma<1, true><<<gF, 256, GEMM_SMEM>>>(Hh, Hl, Wh + OFF_W1, Wl + OFF_W1,
        b1, nullptr, nullptr, Fh, Fl, MROWS, FDIM, CDIM, 1.0f);
    gemm_mma<0, true><<<gC, 256, GEMM_SMEM>>>(Fh, Fl, Wh + OFF_W2, Wl + OFF_W2,
        b2, x1, out, Hh, Hl, MROWS, CDIM, FDIM, 1.0f);

    // ---- bottleneck adapter ----
    gemm_mma<1, true><<<gA, 256, GEMM_SMEM>>>(Hh, Hl, Wh + OFF_WDS, Wl + OFF_WDS,
        bds, nullptr, nullptr, Dh, Dl, MROWS, ADIM, CDIM, 1.0f);
    gemm_mma<0, false><<<gC, 256, GEMM_SMEM>>>(Dh, Dl, Wh + OFF_WUS, Wl + OFF_WUS,
        bus, out, out, nullptr, nullptr, MROWS, CDIM, ADIM, 1.0f);
}

// round 5
// speedup vs baseline: 4.9183x; 2.4449x over previous
#include <cuda_runtime.h>
#include <cuda_fp16.h>
#include <math.h>
#include <stdint.h>

// ---------------- problem constants ----------------
#define BATCH   4
#define SEQ     1500
#define CDIM    1024
#define NHEAD   16
#define HDIM    64
#define FDIM    4096
#define ADIM    256
#define MROWS   (BATCH * SEQ)          // 6000
#define QKSCALE 0.35355339059327379f   // 64^-0.25
#define LOG2E   1.4426950408889634f

// ---------------- scratch ----------------
__device__ float g_x1[MROWS * CDIM];

// fp16 QKV in [B,H,S,D]
__device__ __half g_q[MROWS * CDIM];
__device__ __half g_k[MROWS * CDIM];
__device__ __half g_v[MROWS * CDIM];

__device__ __half g_H[MROWS * CDIM];   // LN out / attn out / adapter in
__device__ __half g_F[MROWS * FDIM];   // MLP hidden
__device__ __half g_D[MROWS * ADIM];   // adapter hidden

#define CC      (CDIM * CDIM)
#define W1SZ    (FDIM * CDIM)
#define ASZ     (ADIM * CDIM)
#define OFF_WQ  0
#define OFF_WK  (CC)
#define OFF_WV  (2 * CC)
#define OFF_WO  (3 * CC)
#define OFF_W1  (4 * CC)
#define OFF_W2  (4 * CC + W1SZ)
#define OFF_WDS (4 * CC + 2 * W1SZ)
#define OFF_WUS (4 * CC + 2 * W1SZ + ASZ)
#define WTOT    (4 * CC + 2 * W1SZ + 2 * ASZ)
__device__ __half g_W[WTOT];

// ---------------- helpers ----------------
__device__ __forceinline__ float gelu_exact(float v) {
    return 0.5f * v * (1.0f + erff(v * 0.70710678118654752f));
}
__device__ __forceinline__ uint32_t smem_u32(const void* p) {
    uint32_t a;
    asm("{ .reg .u64 t; cvta.to.shared.u64 t, %1; cvt.u32.u64 %0, t; }" : "=r"(a) : "l"(p));
    return a;
}
__device__ __forceinline__ void cp_async16(uint32_t dst, const void* src) {
    asm volatile("cp.async.cg.shared.global [%0], [%1], 16;" :: "r"(dst), "l"(src));
}
__device__ __forceinline__ void ldsm_x4(uint32_t& r0, uint32_t& r1, uint32_t& r2,
                                        uint32_t& r3, uint32_t addr) {
    asm volatile("ldmatrix.sync.aligned.m8n8.x4.shared.b16 {%0,%1,%2,%3}, [%4];"
        : "=r"(r0), "=r"(r1), "=r"(r2), "=r"(r3) : "r"(addr));
}
__device__ __forceinline__ void ldsm_x4t(uint32_t& r0, uint32_t& r1, uint32_t& r2,
                                         uint32_t& r3, uint32_t addr) {
    asm volatile("ldmatrix.sync.aligned.m8n8.x4.trans.shared.b16 {%0,%1,%2,%3}, [%4];"
        : "=r"(r0), "=r"(r1), "=r"(r2), "=r"(r3) : "r"(addr));
}
__device__ __forceinline__ void mma_f16(float* c, const uint32_t* a, const uint32_t* b) {
    asm volatile("mma.sync.aligned.m16n8k16.row.col.f32.f16.f16.f32 "
        "{%0,%1,%2,%3}, {%4,%5,%6,%7}, {%8,%9}, {%0,%1,%2,%3};"
        : "+f"(c[0]), "+f"(c[1]), "+f"(c[2]), "+f"(c[3])
        : "r"(a[0]), "r"(a[1]), "r"(a[2]), "r"(a[3]), "r"(b[0]), "r"(b[1]));
}
__device__ __forceinline__ uint32_t packh2(float a, float b) {
    __half2 h = __floats2half2_rn(a, b);
    return *reinterpret_cast<uint32_t*>(&h);
}
#define SWZOFF(row, ch) ((uint32_t)((((row) * 8) + ((ch) ^ ((row) & 7))) * 16))

// ---------------- conversion kernels ----------------
__global__ __launch_bounds__(256) void cvt_kernel(const float* __restrict__ s,
                                                  __half* __restrict__ d, int n4) {
    int i = blockIdx.x * 256 + threadIdx.x;
    if (i >= n4) return;
    float4 v = reinterpret_cast<const float4*>(s)[i];
    __half2* dp = reinterpret_cast<__half2*>(d + (size_t)i * 4);
    dp[0] = __floats2half2_rn(v.x, v.y);
    dp[1] = __floats2half2_rn(v.z, v.w);
}

__global__ __launch_bounds__(256) void ln_h_kernel(const float* __restrict__ x,
                                                   const float* __restrict__ w,
                                                   const float* __restrict__ b,
                                                   __half* __restrict__ oh) {
    __shared__ float red[2][8];
    const int row = blockIdx.x;
    const int tid = threadIdx.x;
    const int lane = tid & 31, wid = tid >> 5;

    float4 v = reinterpret_cast<const float4*>(x + (size_t)row * CDIM)[tid];
    float s  = v.x + v.y + v.z + v.w;
    float ss = v.x*v.x + v.y*v.y + v.z*v.z + v.w*v.w;
    #pragma unroll
    for (int o = 16; o; o >>= 1) {
        s  += __shfl_xor_sync(0xffffffffu, s,  o);
        ss += __shfl_xor_sync(0xffffffffu, ss, o);
    }
    if (lane == 0) { red[0][wid] = s; red[1][wid] = ss; }
    __syncthreads();
    float fs = 0.f, fss = 0.f;
    #pragma unroll
    for (int i = 0; i < 8; i++) { fs += red[0][i]; fss += red[1][i]; }
    const float mu  = fs * (1.0f / CDIM);
    const float var = fss * (1.0f / CDIM) - mu * mu;
    const float r   = rsqrtf(var + 1e-5f);

    float4 wv = reinterpret_cast<const float4*>(w)[tid];
    float4 bv = reinterpret_cast<const float4*>(b)[tid];
    float o0 = (v.x - mu) * r * wv.x + bv.x;
    float o1 = (v.y - mu) * r * wv.y + bv.y;
    float o2 = (v.z - mu) * r * wv.z + bv.z;
    float o3 = (v.w - mu) * r * wv.w + bv.w;
    __half2* hp = reinterpret_cast<__half2*>(oh + (size_t)row * CDIM + tid * 4);
    hp[0] = __floats2half2_rn(o0, o1);
    hp[1] = __floats2half2_rn(o2, o3);
}

// ---------------- fp16 tensor-core GEMM (mma.sync) ----------------
// out[M,N] = A[M,K] @ B[N,K]^T
// MODE 0: v = acc+bias(+res) -> fp32 out (optional half copy to Oh)
// MODE 1: v = gelu(acc+bias) -> half out
// MODE 2: v = (acc+bias)*scale -> half out transposed to [B,H,S,D]
#define BK 64
#define TILEB  (128 * BK * 2)         // 16384
#define STAGEB (2 * TILEB)            // 32768
#define GEMM_SMEM (2 * STAGEB)        // 65536

template<int MODE, bool HCOPY>
__global__ __launch_bounds__(256, 2) void gemm_mma(
        const __half* __restrict__ A, const __half* __restrict__ B,
        const float* __restrict__ bias, const float* __restrict__ res,
        float* __restrict__ out, __half* __restrict__ Oh,
        int M, int N, int K, float scale) {
    extern __shared__ char smem[];
    const uint32_t sbase = smem_u32(smem);
    const int tid  = threadIdx.x;
    const int warp = tid >> 5, lane = tid & 31;
    const int bm = blockIdx.y * 128, bn = blockIdx.x * 128;
    const int wm = warp & 3, wn = warp >> 2;

    // loader: 2 tiles (A,B) x 128 threads, 1 row each
    const int ltile = tid >> 7;
    const int lrow = tid & 127;
    const __half* lsrc = ltile ? B : A;
    int gr = ltile ? (bn + lrow) : min(bm + lrow, M - 1);
    const __half* src = lsrc + (size_t)gr * K;
    const uint32_t dtile = sbase + ltile * TILEB;
    uint32_t doff[8];
    #pragma unroll
    for (int c = 0; c < 8; c++) doff[c] = SWZOFF(lrow, c);

    float acc[2][8][4];
    #pragma unroll
    for (int a = 0; a < 2; a++)
        #pragma unroll
        for (int b = 0; b < 8; b++)
            #pragma unroll
            for (int c = 0; c < 4; c++) acc[a][b][c] = 0.f;

    const int nch = K / BK;

    {
        #pragma unroll
        for (int c = 0; c < 8; c++) cp_async16(dtile + doff[c], src + c * 8);
        asm volatile("cp.async.commit_group;");
    }

    const int arow = (lane & 15);
    const int acsel = lane >> 4;
    const int brow = (lane & 7) + ((lane >> 4) & 1) * 8;
    const int bcsel = (lane >> 3) & 1;

    for (int kc = 0; kc < nch; kc++) {
        const int st = kc & 1;
        if (kc + 1 < nch) {
            const uint32_t db = dtile + (st ^ 1) * STAGEB;
            const int k0 = (kc + 1) * BK;
            #pragma unroll
            for (int c = 0; c < 8; c++) cp_async16(db + doff[c], src + k0 + c * 8);
            asm volatile("cp.async.commit_group;");
            asm volatile("cp.async.wait_group 1;");
        } else {
            asm volatile("cp.async.wait_group 0;");
        }
        __syncthreads();

        const uint32_t base = sbase + st * STAGEB;
        const uint32_t aB = base, bB = base + TILEB;

        #pragma unroll
        for (int ks = 0; ks < 4; ks++) {
            uint32_t af[2][4], bf[8][2];
            #pragma unroll
            for (int mt = 0; mt < 2; mt++) {
                const int row = wm * 32 + mt * 16 + arow;
                const uint32_t off = SWZOFF(row, ks * 2 + acsel);
                ldsm_x4(af[mt][0], af[mt][1], af[mt][2], af[mt][3], aB + off);
            }
            #pragma unroll
            for (int np = 0; np < 4; np++) {
                const int row = wn * 64 + np * 16 + brow;
                const uint32_t off = SWZOFF(row, ks * 2 + bcsel);
                uint32_t r0, r1, r2, r3;
                ldsm_x4(r0, r1, r2, r3, bB + off);
                bf[np*2][0] = r0; bf[np*2][1] = r1; bf[np*2+1][0] = r2; bf[np*2+1][1] = r3;
            }
            #pragma unroll
            for (int mt = 0; mt < 2; mt++)
                #pragma unroll
                for (int nt = 0; nt < 8; nt++)
                    mma_f16(acc[mt][nt], af[mt], bf[nt]);
        }
        __syncthreads();
    }

    const int g = lane >> 2, t = lane & 3;
    #pragma unroll
    for (int mt = 0; mt < 2; mt++) {
        #pragma unroll
        for (int half = 0; half < 2; half++) {
            const int m = bm + wm * 32 + mt * 16 + g + half * 8;
            if (m >= M) continue;
            int bI = 0, sI = 0;
            if (MODE == 2) { bI = m / SEQ; sI = m - bI * SEQ; }
            #pragma unroll
            for (int nt = 0; nt < 8; nt++) {
                const int n = bn + wn * 64 + nt * 8 + t * 2;
                float v0 = acc[mt][nt][half * 2 + 0];
                float v1 = acc[mt][nt][half * 2 + 1];
                if (bias) {
                    float2 b2 = *reinterpret_cast<const float2*>(bias + n);
                    v0 += b2.x; v1 += b2.y;
                }
                if (MODE == 2) {
                    v0 *= scale; v1 *= scale;
                    const int hd = n >> 6, dd = n & 63;
                    const size_t idx = (((size_t)bI * NHEAD + hd) * SEQ + sI) * HDIM + dd;
                    *reinterpret_cast<__half2*>(Oh + idx) = __floats2half2_rn(v0, v1);
                } else if (MODE == 1) {
                    v0 = gelu_exact(v0); v1 = gelu_exact(v1);
                    const size_t idx = (size_t)m * N + n;
                    *reinterpret_cast<__half2*>(Oh + idx) = __floats2half2_rn(v0, v1);
                } else {
                    const size_t idx = (size_t)m * N + n;
                    if (res) {
                        float2 r2 = *reinterpret_cast<const float2*>(res + idx);
                        v0 += r2.x; v1 += r2.y;
                    }
                    *reinterpret_cast<float2*>(out + idx) = make_float2(v0, v1);
                    if (HCOPY)
                        *reinterpret_cast<__half2*>(Oh + idx) = __floats2half2_rn(v0, v1);
                }
            }
        }
    }
}

// ---------------- tensor-core flash attention (fp16) ----------------
#define ATQ 128
#define ATK 64
#define QTILE_B (ATQ * 128)            // 16384
#define KTILE_B (ATK * 128)            // 8192
#define AT_ST0  (QTILE_B)              // KV stages start
#define AT_STAGE (2 * KTILE_B)         // 16384 (K + V)
#define ATT_SMEM (QTILE_B + 2 * AT_STAGE)   // 49152

__global__ __launch_bounds__(256, 2) void attn_mma(
        const __half* __restrict__ Q, const __half* __restrict__ Kp,
        const __half* __restrict__ V, __half* __restrict__ O) {
    extern __shared__ char smem[];
    const uint32_t sbase = smem_u32(smem);
    const int tid = threadIdx.x;
    const int warp = tid >> 5, lane = tid & 31;
    const int b = blockIdx.z, h = blockIdx.y;
    const int q0 = blockIdx.x * ATQ;
    const size_t hb = (size_t)(b * NHEAD + h) * SEQ;
    const int ntiles = (SEQ + ATK - 1) / ATK;   // 24

    // Q load: 256 threads, row = tid>>1, chunks (tid&1)*4..+3
    {
        const int row = tid >> 1;
        const int qr = min(q0 + row, SEQ - 1);
        const __half* sp = Q + (hb + qr) * HDIM;
        #pragma unroll
        for (int c = 0; c < 4; c++) {
            const int ch = (tid & 1) * 4 + c;
            cp_async16(sbase + SWZOFF(row, ch), sp + ch * 8);
        }
    }
    // KV loader: arr = tid>>7 (K,V), row = (tid>>1)&63, chunks (tid&1)*4..+3
    const int kva = tid >> 7;
    const int kvr = (tid >> 1) & 63;
    const __half* kvsrc = kva ? V : Kp;
    const uint32_t kvdst = sbase + AT_ST0 + kva * KTILE_B;
    #define LOADKV(tt, st) do { \
        const int kr_ = min((tt) * ATK + kvr, SEQ - 1); \
        const __half* sp_ = kvsrc + (hb + kr_) * HDIM; \
        const uint32_t db_ = kvdst + (st) * AT_STAGE; \
        _Pragma("unroll") \
        for (int c_ = 0; c_ < 4; c_++) { \
            const int ch_ = (tid & 1) * 4 + c_; \
            cp_async16(db_ + SWZOFF(kvr, ch_), sp_ + ch_ * 8); \
        } \
        asm volatile("cp.async.commit_group;"); \
    } while (0)

    asm volatile("cp.async.commit_group;");   // group for Q
    LOADKV(0, 0);
    LOADKV(1, 1);

    float o[8][4];
    #pragma unroll
    for (int i = 0; i < 8; i++)
        #pragma unroll
        for (int j = 0; j < 4; j++) o[i][j] = 0.f;
    float m0 = -1e30f, m1 = -1e30f, l0 = 0.f, l1 = 0.f;
    uint32_t qf[4][4];
    const int tq = lane & 3;

    for (int t = 0; t < ntiles; t++) {
        if (t + 1 < ntiles) asm volatile("cp.async.wait_group 1;");
        else                asm volatile("cp.async.wait_group 0;");
        __syncthreads();

        if (t == 0) {
            #pragma unroll
            for (int ks = 0; ks < 4; ks++) {
                const int row = warp * 16 + (lane & 15);
                const uint32_t off = SWZOFF(row, ks * 2 + (lane >> 4));
                ldsm_x4(qf[ks][0], qf[ks][1], qf[ks][2], qf[ks][3], sbase + off);
            }
        }

        const uint32_t kb = sbase + AT_ST0 + (t & 1) * AT_STAGE;

        // ---- S = Q K^T ----
        float c[8][4];
        #pragma unroll
        for (int i = 0; i < 8; i++)
            #pragma unroll
            for (int j = 0; j < 4; j++) c[i][j] = 0.f;

        #pragma unroll
        for (int ks = 0; ks < 4; ks++) {
            uint32_t bf[8][2];
            #pragma unroll
            for (int np = 0; np < 4; np++) {
                const int row = np * 16 + (lane & 7) + ((lane >> 4) & 1) * 8;
                const uint32_t off = SWZOFF(row, ks * 2 + ((lane >> 3) & 1));
                uint32_t r0, r1, r2, r3;
                ldsm_x4(r0, r1, r2, r3, kb + off);
                bf[np*2][0] = r0; bf[np*2][1] = r1; bf[np*2+1][0] = r2; bf[np*2+1][1] = r3;
            }
            #pragma unroll
            for (int nt = 0; nt < 8; nt++)
                mma_f16(c[nt], qf[ks], bf[nt]);
        }

        // ---- online softmax ----
        float tmax0 = -1e30f, tmax1 = -1e30f;
        #pragma unroll
        for (int nt = 0; nt < 8; nt++) {
            tmax0 = fmaxf(tmax0, fmaxf(c[nt][0], c[nt][1]));
            tmax1 = fmaxf(tmax1, fmaxf(c[nt][2], c[nt][3]));
        }
        tmax0 = fmaxf(tmax0, __shfl_xor_sync(0xffffffffu, tmax0, 1));
        tmax0 = fmaxf(tmax0, __shfl_xor_sync(0xffffffffu, tmax0, 2));
        tmax1 = fmaxf(tmax1, __shfl_xor_sync(0xffffffffu, tmax1, 1));
        tmax1 = fmaxf(tmax1, __shfl_xor_sync(0xffffffffu, tmax1, 2));
        const float nm0 = fmaxf(m0, tmax0), nm1 = fmaxf(m1, tmax1);
        const float corr0 = exp2f((m0 - nm0) * LOG2E);
        const float corr1 = exp2f((m1 - nm1) * LOG2E);
        #pragma unroll
        for (int nt = 0; nt < 8; nt++) {
            o[nt][0] *= corr0; o[nt][1] *= corr0;
            o[nt][2] *= corr1; o[nt][3] *= corr1;
        }
        float rs0 = 0.f, rs1 = 0.f;
        const bool needmask = (t * ATK + ATK > SEQ);
        #pragma unroll
        for (int nt = 0; nt < 8; nt++) {
            float p00 = exp2f((c[nt][0] - nm0) * LOG2E);
            float p01 = exp2f((c[nt][1] - nm0) * LOG2E);
            float p10 = exp2f((c[nt][2] - nm1) * LOG2E);
            float p11 = exp2f((c[nt][3] - nm1) * LOG2E);
            if (needmask) {
                const int jc = t * ATK + nt * 8 + tq * 2;
                if (jc >= SEQ)     { p00 = 0.f; p10 = 0.f; }
                if (jc + 1 >= SEQ) { p01 = 0.f; p11 = 0.f; }
            }
            rs0 += p00 + p01; rs1 += p10 + p11;
            c[nt][0] = p00; c[nt][1] = p01; c[nt][2] = p10; c[nt][3] = p11;
        }
        rs0 += __shfl_xor_sync(0xffffffffu, rs0, 1);
        rs0 += __shfl_xor_sync(0xffffffffu, rs0, 2);
        rs1 += __shfl_xor_sync(0xffffffffu, rs1, 1);
        rs1 += __shfl_xor_sync(0xffffffffu, rs1, 2);
        l0 = l0 * corr0 + rs0;
        l1 = l1 * corr1 + rs1;
        m0 = nm0; m1 = nm1;

        // ---- pack P into fp16 A fragments ----
        uint32_t pa[4][4];
        #pragma unroll
        for (int ks = 0; ks < 4; ks++) {
            pa[ks][0] = packh2(c[2*ks][0],   c[2*ks][1]);
            pa[ks][1] = packh2(c[2*ks][2],   c[2*ks][3]);
            pa[ks][2] = packh2(c[2*ks+1][0], c[2*ks+1][1]);
            pa[ks][3] = packh2(c[2*ks+1][2], c[2*ks+1][3]);
        }

        // ---- O += P V ----
        #pragma unroll
        for (int ks = 0; ks < 4; ks++) {
            uint32_t vf[8][2];
            #pragma unroll
            for (int np = 0; np < 4; np++) {
                const int row = ks * 16 + (lane & 7) + ((lane >> 3) & 1) * 8;
                const uint32_t off = SWZOFF(row, np * 2 + (lane >> 4));
                uint32_t r0, r1, r2, r3;
                ldsm_x4t(r0, r1, r2, r3, kb + KTILE_B + off);
                vf[np*2][0] = r0; vf[np*2][1] = r1; vf[np*2+1][0] = r2; vf[np*2+1][1] = r3;
            }
            #pragma unroll
            for (int nt = 0; nt < 8; nt++)
                mma_f16(o[nt], pa[ks], vf[nt]);
        }
        __syncthreads();
        if (t + 2 < ntiles) LOADKV(t + 2, t & 1);
    }

    // ---- epilogue ----
    const float inv0 = 1.0f / l0, inv1 = 1.0f / l1;
    const int token0 = q0 + warp * 16 + (lane >> 2);
    const int token1 = token0 + 8;
    #pragma unroll
    for (int nt = 0; nt < 8; nt++) {
        const int d0 = nt * 8 + tq * 2;
        if (token0 < SEQ) {
            const size_t idx = (size_t)(b * SEQ + token0) * CDIM + h * HDIM + d0;
            *reinterpret_cast<__half2*>(O + idx) =
                __floats2half2_rn(o[nt][0] * inv0, o[nt][1] * inv0);
        }
        if (token1 < SEQ) {
            const size_t idx = (size_t)(b * SEQ + token1) * CDIM + h * HDIM + d0;
            *reinterpret_cast<__half2*>(O + idx) =
                __floats2half2_rn(o[nt][2] * inv1, o[nt][3] * inv1);
        }
    }
}

// ---------------- launch ----------------
extern "C" void kernel_launch(void* const* d_in, const int* in_sizes, int n_in,
                              void* d_out, int out_size) {
    const float* x     = (const float*)d_in[0];
    const float* Wq    = (const float*)d_in[1];
    const float* bq    = (const float*)d_in[2];
    const float* Wk    = (const float*)d_in[3];
    const float* Wv    = (const float*)d_in[4];
    const float* bv    = (const float*)d_in[5];
    const float* Wo    = (const float*)d_in[6];
    const float* bo    = (const float*)d_in[7];
    const float* ln_aw = (const float*)d_in[8];
    const float* ln_ab = (const float*)d_in[9];
    const float* W1    = (const float*)d_in[10];
    const float* b1    = (const float*)d_in[11];
    const float* W2    = (const float*)d_in[12];
    const float* b2    = (const float*)d_in[13];
    const float* ln_mw = (const float*)d_in[14];
    const float* ln_mb = (const float*)d_in[15];
    const float* Wds   = (const float*)d_in[16];
    const float* bds   = (const float*)d_in[17];
    const float* Wus   = (const float*)d_in[18];
    const float* bus   = (const float*)d_in[19];
    float* out = (float*)d_out;

    float *x1;
    __half *q, *k, *v, *H, *F, *D, *W;
    cudaGetSymbolAddress((void**)&x1, g_x1);
    cudaGetSymbolAddress((void**)&q,  g_q);
    cudaGetSymbolAddress((void**)&k,  g_k);
    cudaGetSymbolAddress((void**)&v,  g_v);
    cudaGetSymbolAddress((void**)&H,  g_H);
    cudaGetSymbolAddress((void**)&F,  g_F);
    cudaGetSymbolAddress((void**)&D,  g_D);
    cudaGetSymbolAddress((void**)&W,  g_W);

    cudaFuncSetAttribute(gemm_mma<0, false>, cudaFuncAttributeMaxDynamicSharedMemorySize, GEMM_SMEM);
    cudaFuncSetAttribute(gemm_mma<0, true>,  cudaFuncAttributeMaxDynamicSharedMemorySize, GEMM_SMEM);
    cudaFuncSetAttribute(gemm_mma<1, true>,  cudaFuncAttributeMaxDynamicSharedMemorySize, GEMM_SMEM);
    cudaFuncSetAttribute(gemm_mma<2, false>, cudaFuncAttributeMaxDynamicSharedMemorySize, GEMM_SMEM);
    cudaFuncSetAttribute(attn_mma, cudaFuncAttributeMaxDynamicSharedMemorySize, ATT_SMEM);

    auto cvtw = [&](const float* src, int off, int n) {
        cvt_kernel<<<(n / 4 + 255) / 256, 256>>>(src, W + off, n / 4);
    };
    cvtw(Wq,  OFF_WQ,  CC);
    cvtw(Wk,  OFF_WK,  CC);
    cvtw(Wv,  OFF_WV,  CC);
    cvtw(Wo,  OFF_WO,  CC);
    cvtw(W1,  OFF_W1,  W1SZ);
    cvtw(W2,  OFF_W2,  W1SZ);
    cvtw(Wds, OFF_WDS, ASZ);
    cvtw(Wus, OFF_WUS, ASZ);

    const int mg = (MROWS + 127) / 128;
    dim3 gC(CDIM / 128, mg);
    dim3 gF(FDIM / 128, mg);
    dim3 gA(ADIM / 128, mg);
    dim3 gAt((SEQ + ATQ - 1) / ATQ, NHEAD, BATCH);

    // ---- attention ----
    ln_h_kernel<<<MROWS, 256>>>(x, ln_aw, ln_ab, H);
    gemm_mma<2, false><<<gC, 256, GEMM_SMEM>>>(H, W + OFF_WQ, bq, nullptr,
        nullptr, q, MROWS, CDIM, CDIM, QKSCALE);
    gemm_mma<2, false><<<gC, 256, GEMM_SMEM>>>(H, W + OFF_WK, nullptr, nullptr,
        nullptr, k, MROWS, CDIM, CDIM, QKSCALE);
    gemm_mma<2, false><<<gC, 256, GEMM_SMEM>>>(H, W + OFF_WV, bv, nullptr,
        nullptr, v, MROWS, CDIM, CDIM, 1.0f);
    attn_mma<<<gAt, 256, ATT_SMEM>>>(q, k, v, H);
    gemm_mma<0, false><<<gC, 256, GEMM_SMEM>>>(H, W + OFF_WO, bo, x,
        x1, nullptr, MROWS, CDIM, CDIM, 1.0f);

    // ---- MLP ----
    ln_h_kernel<<<MROWS, 256>>>(x1, ln_mw, ln_mb, H);
    gemm_mma<1, true><<<gF, 256, GEMM_SMEM>>>(H, W + OFF_W1, b1, nullptr,
        nullptr, F, MROWS, FDIM, CDIM, 1.0f);
    gemm_mma<0, true><<<gC, 256, GEMM_SMEM>>>(F, W + OFF_W2, b2, x1,
        out, H, MROWS, CDIM, FDIM, 1.0f);

    // ---- bottleneck adapter ----
    gemm_mma<1, true><<<gA, 256, GEMM_SMEM>>>(H, W + OFF_WDS, bds, nullptr,
        nullptr, D, MROWS, ADIM, CDIM, 1.0f);
    gemm_mma<0, false><<<gC, 256, GEMM_SMEM>>>(D, W + OFF_WUS, bus, out,
        out, nullptr, MROWS, CDIM, ADIM, 1.0f);
}

// round 7
// speedup vs baseline: 5.1254x; 1.0421x over previous
#include <cuda_runtime.h>
#include <cuda_fp16.h>
#include <math.h>
#include <stdint.h>

// ---------------- problem constants ----------------
#define BATCH   4
#define SEQ     1500
#define CDIM    1024
#define NHEAD   16
#define HDIM    64
#define FDIM    4096
#define ADIM    256
#define MROWS   (BATCH * SEQ)          // 6000
#define QKSCALE 0.35355339059327379f   // 64^-0.25
#define LOG2E   1.4426950408889634f

// ---------------- scratch ----------------
__device__ float g_x1[MROWS * CDIM];

__device__ __half g_q[MROWS * CDIM];
__device__ __half g_k[MROWS * CDIM];
__device__ __half g_v[MROWS * CDIM];

__device__ __half g_H[MROWS * CDIM];
__device__ __half g_F[MROWS * FDIM];
__device__ __half g_D[MROWS * ADIM];

#define CC      (CDIM * CDIM)
#define W1SZ    (FDIM * CDIM)
#define ASZ     (ADIM * CDIM)
#define OFF_WQ  0
#define OFF_WK  (CC)
#define OFF_WV  (2 * CC)
#define OFF_WO  (3 * CC)
#define OFF_W1  (4 * CC)
#define OFF_W2  (4 * CC + W1SZ)
#define OFF_WDS (4 * CC + 2 * W1SZ)
#define OFF_WUS (4 * CC + 2 * W1SZ + ASZ)
#define WTOT    (4 * CC + 2 * W1SZ + 2 * ASZ)
__device__ __half g_W[WTOT];

// ---------------- helpers ----------------
__device__ __forceinline__ float gelu_exact(float v) {
    return 0.5f * v * (1.0f + erff(v * 0.70710678118654752f));
}
__device__ __forceinline__ uint32_t smem_u32(const void* p) {
    uint32_t a;
    asm("{ .reg .u64 t; cvta.to.shared.u64 t, %1; cvt.u32.u64 %0, t; }" : "=r"(a) : "l"(p));
    return a;
}
__device__ __forceinline__ void cp_async16(uint32_t dst, const void* src) {
    asm volatile("cp.async.cg.shared.global [%0], [%1], 16;" :: "r"(dst), "l"(src));
}
__device__ __forceinline__ void ldsm_x4(uint32_t& r0, uint32_t& r1, uint32_t& r2,
                                        uint32_t& r3, uint32_t addr) {
    asm volatile("ldmatrix.sync.aligned.m8n8.x4.shared.b16 {%0,%1,%2,%3}, [%4];"
        : "=r"(r0), "=r"(r1), "=r"(r2), "=r"(r3) : "r"(addr));
}
__device__ __forceinline__ void ldsm_x4t(uint32_t& r0, uint32_t& r1, uint32_t& r2,
                                         uint32_t& r3, uint32_t addr) {
    asm volatile("ldmatrix.sync.aligned.m8n8.x4.trans.shared.b16 {%0,%1,%2,%3}, [%4];"
        : "=r"(r0), "=r"(r1), "=r"(r2), "=r"(r3) : "r"(addr));
}
__device__ __forceinline__ void mma_f16(float* c, const uint32_t* a, const uint32_t* b) {
    asm volatile("mma.sync.aligned.m16n8k16.row.col.f32.f16.f16.f32 "
        "{%0,%1,%2,%3}, {%4,%5,%6,%7}, {%8,%9}, {%0,%1,%2,%3};"
        : "+f"(c[0]), "+f"(c[1]), "+f"(c[2]), "+f"(c[3])
        : "r"(a[0]), "r"(a[1]), "r"(a[2]), "r"(a[3]), "r"(b[0]), "r"(b[1]));
}
__device__ __forceinline__ uint32_t packh2(float a, float b) {
    __half2 h = __floats2half2_rn(a, b);
    return *reinterpret_cast<uint32_t*>(&h);
}
#define SWZOFF(row, ch) ((uint32_t)((((row) * 8) + ((ch) ^ ((row) & 7))) * 16))

// ---------------- fused weight conversion ----------------
struct CvtArgs {
    const float* src[8];
    int off4[9];   // prefix offsets in float4 units into g_W
};
__global__ __launch_bounds__(256) void cvt_all_kernel(CvtArgs a, __half* __restrict__ W) {
    const int i = blockIdx.x * 256 + threadIdx.x;
    if (i >= a.off4[8]) return;
    int seg = 0;
    #pragma unroll
    for (int s = 1; s < 8; s++) if (i >= a.off4[s]) seg = s;
    const int li = i - a.off4[seg];
    float4 v = reinterpret_cast<const float4*>(a.src[seg])[li];
    __half2* dp = reinterpret_cast<__half2*>(W + (size_t)i * 4);
    dp[0] = __floats2half2_rn(v.x, v.y);
    dp[1] = __floats2half2_rn(v.z, v.w);
}

__global__ __launch_bounds__(256) void ln_h_kernel(const float* __restrict__ x,
                                                   const float* __restrict__ w,
                                                   const float* __restrict__ b,
                                                   __half* __restrict__ oh) {
    __shared__ float red[2][8];
    const int row = blockIdx.x;
    const int tid = threadIdx.x;
    const int lane = tid & 31, wid = tid >> 5;

    float4 v = reinterpret_cast<const float4*>(x + (size_t)row * CDIM)[tid];
    float s  = v.x + v.y + v.z + v.w;
    float ss = v.x*v.x + v.y*v.y + v.z*v.z + v.w*v.w;
    #pragma unroll
    for (int o = 16; o; o >>= 1) {
        s  += __shfl_xor_sync(0xffffffffu, s,  o);
        ss += __shfl_xor_sync(0xffffffffu, ss, o);
    }
    if (lane == 0) { red[0][wid] = s; red[1][wid] = ss; }
    __syncthreads();
    float fs = 0.f, fss = 0.f;
    #pragma unroll
    for (int i = 0; i < 8; i++) { fs += red[0][i]; fss += red[1][i]; }
    const float mu  = fs * (1.0f / CDIM);
    const float var = fss * (1.0f / CDIM) - mu * mu;
    const float r   = rsqrtf(var + 1e-5f);

    float4 wv = reinterpret_cast<const float4*>(w)[tid];
    float4 bv = reinterpret_cast<const float4*>(b)[tid];
    float o0 = (v.x - mu) * r * wv.x + bv.x;
    float o1 = (v.y - mu) * r * wv.y + bv.y;
    float o2 = (v.z - mu) * r * wv.z + bv.z;
    float o3 = (v.w - mu) * r * wv.w + bv.w;
    __half2* hp = reinterpret_cast<__half2*>(oh + (size_t)row * CDIM + tid * 4);
    hp[0] = __floats2half2_rn(o0, o1);
    hp[1] = __floats2half2_rn(o2, o3);
}

// ---------------- fp16 tensor-core GEMM, 3-stage cp.async pipeline ----------------
// out[M,N] = A[M,K] @ B[N,K]^T
// MODE 0: v = acc+bias(+res) -> fp32 out (optional half copy to Oh)
// MODE 1: v = gelu(acc+bias) -> half out (Oh)
// MODE 3: fused QKV: segment by bn>>10 -> (Oh=q w/ bias,scale | Kp w/ scale | Vp w/ bias2)
//         transposed write to [B,H,S,D]
#define BK 64
#define TILEB  (128 * BK * 2)         // 16384
#define STAGEB (2 * TILEB)            // 32768 (A+B)
#define NSTAGE 3
#define GEMM_SMEM (NSTAGE * STAGEB)   // 98304

template<int MODE, bool HCOPY>
__global__ __launch_bounds__(256, 2) void gemm_mma(
        const __half* __restrict__ A, const __half* __restrict__ B,
        const float* __restrict__ bias, const float* __restrict__ bias2,
        const float* __restrict__ res,
        float* __restrict__ out, __half* __restrict__ Oh,
        __half* __restrict__ Kp, __half* __restrict__ Vp,
        int M, int N, int K, float scale) {
    extern __shared__ char smem[];
    const uint32_t sbase = smem_u32(smem);
    const int tid  = threadIdx.x;
    const int warp = tid >> 5, lane = tid & 31;
    const int bm = blockIdx.y * 128, bn = blockIdx.x * 128;
    const int wm = warp & 3, wn = warp >> 2;

    // loader: 2 tiles (A,B) x 128 threads, 1 row each
    const int ltile = tid >> 7;
    const int lrow = tid & 127;
    const __half* lsrc = ltile ? B : A;
    int gr = ltile ? (bn + lrow) : min(bm + lrow, M - 1);
    const __half* src = lsrc + (size_t)gr * K;
    const uint32_t dtile = sbase + ltile * TILEB;
    uint32_t doff[8];
    #pragma unroll
    for (int c = 0; c < 8; c++) doff[c] = SWZOFF(lrow, c);

    float acc[2][8][4];
    #pragma unroll
    for (int a = 0; a < 2; a++)
        #pragma unroll
        for (int b = 0; b < 8; b++)
            #pragma unroll
            for (int c = 0; c < 4; c++) acc[a][b][c] = 0.f;

    const int nch = K / BK;

    // prologue: chunks 0 and 1
    #pragma unroll
    for (int p = 0; p < 2; p++) {
        const uint32_t db = dtile + p * STAGEB;
        const int k0 = p * BK;
        #pragma unroll
        for (int c = 0; c < 8; c++) cp_async16(db + doff[c], src + k0 + c * 8);
        asm volatile("cp.async.commit_group;");
    }

    const int arow = (lane & 15);
    const int acsel = lane >> 4;
    const int brow = (lane & 7) + ((lane >> 4) & 1) * 8;
    const int bcsel = (lane >> 3) & 1;

    int stc = 0;   // stage of current compute chunk
    for (int kc = 0; kc < nch; kc++) {
        if (kc + 1 < nch) asm volatile("cp.async.wait_group 1;");
        else              asm volatile("cp.async.wait_group 0;");
        __syncthreads();

        // issue load for chunk kc+2 into the stage freed last iteration
        if (kc + 2 < nch) {
            const int stn = (stc + 2 >= NSTAGE) ? (stc + 2 - NSTAGE) : (stc + 2);
            const uint32_t db = dtile + stn * STAGEB;
            const int k0 = (kc + 2) * BK;
            #pragma unroll
            for (int c = 0; c < 8; c++) cp_async16(db + doff[c], src + k0 + c * 8);
            asm volatile("cp.async.commit_group;");
        }

        const uint32_t base = sbase + stc * STAGEB;
        const uint32_t aB = base, bB = base + TILEB;

        #pragma unroll
        for (int ks = 0; ks < 4; ks++) {
            uint32_t af[2][4], bf[8][2];
            #pragma unroll
            for (int mt = 0; mt < 2; mt++) {
                const int row = wm * 32 + mt * 16 + arow;
                const uint32_t off = SWZOFF(row, ks * 2 + acsel);
                ldsm_x4(af[mt][0], af[mt][1], af[mt][2], af[mt][3], aB + off);
            }
            #pragma unroll
            for (int np = 0; np < 4; np++) {
                const int row = wn * 64 + np * 16 + brow;
                const uint32_t off = SWZOFF(row, ks * 2 + bcsel);
                uint32_t r0, r1, r2, r3;
                ldsm_x4(r0, r1, r2, r3, bB + off);
                bf[np*2][0] = r0; bf[np*2][1] = r1; bf[np*2+1][0] = r2; bf[np*2+1][1] = r3;
            }
            #pragma unroll
            for (int mt = 0; mt < 2; mt++)
                #pragma unroll
                for (int nt = 0; nt < 8; nt++)
                    mma_f16(acc[mt][nt], af[mt], bf[nt]);
        }
        stc = (stc + 1 == NSTAGE) ? 0 : stc + 1;
    }

    // ---------------- epilogue ----------------
    // MODE 3 routing (constant per CTA since 1024 % 128 == 0)
    __half* dst3 = Oh;
    const float* bb3 = bias;
    float sc3 = scale;
    if (MODE == 3) {
        const int seg = bn >> 10;
        dst3 = (seg == 0) ? Oh : ((seg == 1) ? Kp : Vp);
        bb3  = (seg == 0) ? bias : ((seg == 2) ? bias2 : nullptr);
        sc3  = (seg < 2) ? scale : 1.0f;
    }

    const int g = lane >> 2, t = lane & 3;
    #pragma unroll
    for (int mt = 0; mt < 2; mt++) {
        #pragma unroll
        for (int half = 0; half < 2; half++) {
            const int m = bm + wm * 32 + mt * 16 + g + half * 8;
            if (m >= M) continue;
            int bI = 0, sI = 0;
            if (MODE == 3) { bI = m / SEQ; sI = m - bI * SEQ; }
            #pragma unroll
            for (int nt = 0; nt < 8; nt++) {
                const int n = bn + wn * 64 + nt * 8 + t * 2;
                float v0 = acc[mt][nt][half * 2 + 0];
                float v1 = acc[mt][nt][half * 2 + 1];
                if (MODE == 3) {
                    const int nn = n & 1023;
                    if (bb3) {
                        float2 b2 = *reinterpret_cast<const float2*>(bb3 + nn);
                        v0 += b2.x; v1 += b2.y;
                    }
                    v0 *= sc3; v1 *= sc3;
                    const int hd = nn >> 6, dd = nn & 63;
                    const size_t idx = (((size_t)bI * NHEAD + hd) * SEQ + sI) * HDIM + dd;
                    *reinterpret_cast<__half2*>(dst3 + idx) = __floats2half2_rn(v0, v1);
                } else {
                    if (bias) {
                        float2 b2 = *reinterpret_cast<const float2*>(bias + n);
                        v0 += b2.x; v1 += b2.y;
                    }
                    if (MODE == 1) {
                        v0 = gelu_exact(v0); v1 = gelu_exact(v1);
                        const size_t idx = (size_t)m * N + n;
                        *reinterpret_cast<__half2*>(Oh + idx) = __floats2half2_rn(v0, v1);
                    } else {
                        const size_t idx = (size_t)m * N + n;
                        if (res) {
                            float2 r2 = *reinterpret_cast<const float2*>(res + idx);
                            v0 += r2.x; v1 += r2.y;
                        }
                        *reinterpret_cast<float2*>(out + idx) = make_float2(v0, v1);
                        if (HCOPY)
                            *reinterpret_cast<__half2*>(Oh + idx) = __floats2half2_rn(v0, v1);
                    }
                }
            }
        }
    }
}

// ---------------- tensor-core flash attention (fp16) ----------------
#define ATQ 128
#define ATK 64
#define QTILE_B (ATQ * 128)
#define KTILE_B (ATK * 128)
#define AT_ST0  (QTILE_B)
#define AT_STAGE (2 * KTILE_B)
#define ATT_SMEM (QTILE_B + 2 * AT_STAGE)   // 49152

__global__ __launch_bounds__(256, 2) void attn_mma(
        const __half* __restrict__ Q, const __half* __restrict__ Kp,
        const __half* __restrict__ V, __half* __restrict__ O) {
    extern __shared__ char smem[];
    const uint32_t sbase = smem_u32(smem);
    const int tid = threadIdx.x;
    const int warp = tid >> 5, lane = tid & 31;
    const int b = blockIdx.z, h = blockIdx.y;
    const int q0 = blockIdx.x * ATQ;
    const size_t hb = (size_t)(b * NHEAD + h) * SEQ;
    const int ntiles = (SEQ + ATK - 1) / ATK;   // 24

    {
        const int row = tid >> 1;
        const int qr = min(q0 + row, SEQ - 1);
        const __half* sp = Q + (hb + qr) * HDIM;
        #pragma unroll
        for (int c = 0; c < 4; c++) {
            const int ch = (tid & 1) * 4 + c;
            cp_async16(sbase + SWZOFF(row, ch), sp + ch * 8);
        }
    }
    const int kva = tid >> 7;
    const int kvr = (tid >> 1) & 63;
    const __half* kvsrc = kva ? V : Kp;
    const uint32_t kvdst = sbase + AT_ST0 + kva * KTILE_B;
    #define LOADKV(tt, st) do { \
        const int kr_ = min((tt) * ATK + kvr, SEQ - 1); \
        const __half* sp_ = kvsrc + (hb + kr_) * HDIM; \
        const uint32_t db_ = kvdst + (st) * AT_STAGE; \
        _Pragma("unroll") \
        for (int c_ = 0; c_ < 4; c_++) { \
            const int ch_ = (tid & 1) * 4 + c_; \
            cp_async16(db_ + SWZOFF(kvr, ch_), sp_ + ch_ * 8); \
        } \
        asm volatile("cp.async.commit_group;"); \
    } while (0)

    asm volatile("cp.async.commit_group;");
    LOADKV(0, 0);
    LOADKV(1, 1);

    float o[8][4];
    #pragma unroll
    for (int i = 0; i < 8; i++)
        #pragma unroll
        for (int j = 0; j < 4; j++) o[i][j] = 0.f;
    float m0 = -1e30f, m1 = -1e30f, l0 = 0.f, l1 = 0.f;
    uint32_t qf[4][4];
    const int tq = lane & 3;

    for (int t = 0; t < ntiles; t++) {
        if (t + 1 < ntiles) asm volatile("cp.async.wait_group 1;");
        else                asm volatile("cp.async.wait_group 0;");
        __syncthreads();

        if (t == 0) {
            #pragma unroll
            for (int ks = 0; ks < 4; ks++) {
                const int row = warp * 16 + (lane & 15);
                const uint32_t off = SWZOFF(row, ks * 2 + (lane >> 4));
                ldsm_x4(qf[ks][0], qf[ks][1], qf[ks][2], qf[ks][3], sbase + off);
            }
        }

        const uint32_t kb = sbase + AT_ST0 + (t & 1) * AT_STAGE;

        float c[8][4];
        #pragma unroll
        for (int i = 0; i < 8; i++)
            #pragma unroll
            for (int j = 0; j < 4; j++) c[i][j] = 0.f;

        #pragma unroll
        for (int ks = 0; ks < 4; ks++) {
            uint32_t bf[8][2];
            #pragma unroll
            for (int np = 0; np < 4; np++) {
                const int row = np * 16 + (lane & 7) + ((lane >> 4) & 1) * 8;
                const uint32_t off = SWZOFF(row, ks * 2 + ((lane >> 3) & 1));
                uint32_t r0, r1, r2, r3;
                ldsm_x4(r0, r1, r2, r3, kb + off);
                bf[np*2][0] = r0; bf[np*2][1] = r1; bf[np*2+1][0] = r2; bf[np*2+1][1] = r3;
            }
            #pragma unroll
            for (int nt = 0; nt < 8; nt++)
                mma_f16(c[nt], qf[ks], bf[nt]);
        }

        float tmax0 = -1e30f, tmax1 = -1e30f;
        #pragma unroll
        for (int nt = 0; nt < 8; nt++) {
            tmax0 = fmaxf(tmax0, fmaxf(c[nt][0], c[nt][1]));
            tmax1 = fmaxf(tmax1, fmaxf(c[nt][2], c[nt][3]));
        }
        tmax0 = fmaxf(tmax0, __shfl_xor_sync(0xffffffffu, tmax0, 1));
        tmax0 = fmaxf(tmax0, __shfl_xor_sync(0xffffffffu, tmax0, 2));
        tmax1 = fmaxf(tmax1, __shfl_xor_sync(0xffffffffu, tmax1, 1));
        tmax1 = fmaxf(tmax1, __shfl_xor_sync(0xffffffffu, tmax1, 2));
        const float nm0 = fmaxf(m0, tmax0), nm1 = fmaxf(m1, tmax1);
        const float corr0 = exp2f((m0 - nm0) * LOG2E);
        const float corr1 = exp2f((m1 - nm1) * LOG2E);
        #pragma unroll
        for (int nt = 0; nt < 8; nt++) {
            o[nt][0] *= corr0; o[nt][1] *= corr0;
            o[nt][2] *= corr1; o[nt][3] *= corr1;
        }
        float rs0 = 0.f, rs1 = 0.f;
        const bool needmask = (t * ATK + ATK > SEQ);
        #pragma unroll
        for (int nt = 0; nt < 8; nt++) {
            float p00 = exp2f((c[nt][0] - nm0) * LOG2E);
            float p01 = exp2f((c[nt][1] - nm0) * LOG2E);
            float p10 = exp2f((c[nt][2] - nm1) * LOG2E);
            float p11 = exp2f((c[nt][3] - nm1) * LOG2E);
            if (needmask) {
                const int jc = t * ATK + nt * 8 + tq * 2;
                if (jc >= SEQ)     { p00 = 0.f; p10 = 0.f; }
                if (jc + 1 >= SEQ) { p01 = 0.f; p11 = 0.f; }
            }
            rs0 += p00 + p01; rs1 += p10 + p11;
            c[nt][0] = p00; c[nt][1] = p01; c[nt][2] = p10; c[nt][3] = p11;
        }
        rs0 += __shfl_xor_sync(0xffffffffu, rs0, 1);
        rs0 += __shfl_xor_sync(0xffffffffu, rs0, 2);
        rs1 += __shfl_xor_sync(0xffffffffu, rs1, 1);
        rs1 += __shfl_xor_sync(0xffffffffu, rs1, 2);
        l0 = l0 * corr0 + rs0;
        l1 = l1 * corr1 + rs1;
        m0 = nm0; m1 = nm1;

        uint32_t pa[4][4];
        #pragma unroll
        for (int ks = 0; ks < 4; ks++) {
            pa[ks][0] = packh2(c[2*ks][0],   c[2*ks][1]);
            pa[ks][1] = packh2(c[2*ks][2],   c[2*ks][3]);
            pa[ks][2] = packh2(c[2*ks+1][0], c[2*ks+1][1]);
            pa[ks][3] = packh2(c[2*ks+1][2], c[2*ks+1][3]);
        }

        #pragma unroll
        for (int ks = 0; ks < 4; ks++) {
            uint32_t vf[8][2];
            #pragma unroll
            for (int np = 0; np < 4; np++) {
                const int row = ks * 16 + (lane & 7) + ((lane >> 3) & 1) * 8;
                const uint32_t off = SWZOFF(row, np * 2 + (lane >> 4));
                uint32_t r0, r1, r2, r3;
                ldsm_x4t(r0, r1, r2, r3, kb + KTILE_B + off);
                vf[np*2][0] = r0; vf[np*2][1] = r1; vf[np*2+1][0] = r2; vf[np*2+1][1] = r3;
            }
            #pragma unroll
            for (int nt = 0; nt < 8; nt++)
                mma_f16(o[nt], pa[ks], vf[nt]);
        }
        __syncthreads();
        if (t + 2 < ntiles) LOADKV(t + 2, t & 1);
    }

    const float inv0 = 1.0f / l0, inv1 = 1.0f / l1;
    const int token0 = q0 + warp * 16 + (lane >> 2);
    const int token1 = token0 + 8;
    #pragma unroll
    for (int nt = 0; nt < 8; nt++) {
        const int d0 = nt * 8 + tq * 2;
        if (token0 < SEQ) {
            const size_t idx = (size_t)(b * SEQ + token0) * CDIM + h * HDIM + d0;
            *reinterpret_cast<__half2*>(O + idx) =
                __floats2half2_rn(o[nt][0] * inv0, o[nt][1] * inv0);
        }
        if (token1 < SEQ) {
            const size_t idx = (size_t)(b * SEQ + token1) * CDIM + h * HDIM + d0;
            *reinterpret_cast<__half2*>(O + idx) =
                __floats2half2_rn(o[nt][2] * inv1, o[nt][3] * inv1);
        }
    }
}

// ---------------- launch ----------------
extern "C" void kernel_launch(void* const* d_in, const int* in_sizes, int n_in,
                              void* d_out, int out_size) {
    const float* x     = (const float*)d_in[0];
    const float* Wq    = (const float*)d_in[1];
    const float* bq    = (const float*)d_in[2];
    const float* Wk    = (const float*)d_in[3];
    const float* Wv    = (const float*)d_in[4];
    const float* bv    = (const float*)d_in[5];
    const float* Wo    = (const float*)d_in[6];
    const float* bo    = (const float*)d_in[7];
    const float* ln_aw = (const float*)d_in[8];
    const float* ln_ab = (const float*)d_in[9];
    const float* W1    = (const float*)d_in[10];
    const float* b1    = (const float*)d_in[11];
    const float* W2    = (const float*)d_in[12];
    const float* b2    = (const float*)d_in[13];
    const float* ln_mw = (const float*)d_in[14];
    const float* ln_mb = (const float*)d_in[15];
    const float* Wds   = (const float*)d_in[16];
    const float* bds   = (const float*)d_in[17];
    const float* Wus   = (const float*)d_in[18];
    const float* bus   = (const float*)d_in[19];
    float* out = (float*)d_out;

    float *x1;
    __half *q, *k, *v, *H, *F, *D, *W;
    cudaGetSymbolAddress((void**)&x1, g_x1);
    cudaGetSymbolAddress((void**)&q,  g_q);
    cudaGetSymbolAddress((void**)&k,  g_k);
    cudaGetSymbolAddress((void**)&v,  g_v);
    cudaGetSymbolAddress((void**)&H,  g_H);
    cudaGetSymbolAddress((void**)&F,  g_F);
    cudaGetSymbolAddress((void**)&D,  g_D);
    cudaGetSymbolAddress((void**)&W,  g_W);

    cudaFuncSetAttribute(gemm_mma<0, false>, cudaFuncAttributeMaxDynamicSharedMemorySize, GEMM_SMEM);
    cudaFuncSetAttribute(gemm_mma<0, true>,  cudaFuncAttributeMaxDynamicSharedMemorySize, GEMM_SMEM);
    cudaFuncSetAttribute(gemm_mma<1, true>,  cudaFuncAttributeMaxDynamicSharedMemorySize, GEMM_SMEM);
    cudaFuncSetAttribute(gemm_mma<3, false>, cudaFuncAttributeMaxDynamicSharedMemorySize, GEMM_SMEM);
    cudaFuncSetAttribute(attn_mma, cudaFuncAttributeMaxDynamicSharedMemorySize, ATT_SMEM);

    // fused weight convert
    CvtArgs ca;
    ca.src[0] = Wq;  ca.src[1] = Wk;  ca.src[2] = Wv;  ca.src[3] = Wo;
    ca.src[4] = W1;  ca.src[5] = W2;  ca.src[6] = Wds; ca.src[7] = Wus;
    const int seg4[8] = {CC/4, CC/4, CC/4, CC/4, W1SZ/4, W1SZ/4, ASZ/4, ASZ/4};
    ca.off4[0] = 0;
    for (int i = 0; i < 8; i++) ca.off4[i + 1] = ca.off4[i] + seg4[i];
    cvt_all_kernel<<<(ca.off4[8] + 255) / 256, 256>>>(ca, W);

    const int mg = (MROWS + 127) / 128;   // 47
    dim3 gQKV(3 * CDIM / 128, mg);        // (24,47)
    dim3 gC(CDIM / 128, mg);
    dim3 gF(FDIM / 128, mg);
    dim3 gA(ADIM / 128, mg);
    dim3 gAt((SEQ + ATQ - 1) / ATQ, NHEAD, BATCH);

    // ---- attention ----
    ln_h_kernel<<<MROWS, 256>>>(x, ln_aw, ln_ab, H);
    gemm_mma<3, false><<<gQKV, 256, GEMM_SMEM>>>(H, W + OFF_WQ, bq, bv, nullptr,
        nullptr, q, k, v, MROWS, 3 * CDIM, CDIM, QKSCALE);
    attn_mma<<<gAt, 256, ATT_SMEM>>>(q, k, v, H);
    gemm_mma<0, false><<<gC, 256, GEMM_SMEM>>>(H, W + OFF_WO, bo, nullptr, x,
        x1, nullptr, nullptr, nullptr, MROWS, CDIM, CDIM, 1.0f);

    // ---- MLP ----
    ln_h_kernel<<<MROWS, 256>>>(x1, ln_mw, ln_mb, H);
    gemm_mma<1, true><<<gF, 256, GEMM_SMEM>>>(H, W + OFF_W1, b1, nullptr, nullptr,
        nullptr, F, nullptr, nullptr, MROWS, FDIM, CDIM, 1.0f);
    gemm_mma<0, true><<<gC, 256, GEMM_SMEM>>>(F, W + OFF_W2, b2, nullptr, x1,
        out, H, nullptr, nullptr, MROWS, CDIM, FDIM, 1.0f);

    // ---- bottleneck adapter ----
    gemm_mma<1, true><<<gA, 256, GEMM_SMEM>>>(H, W + OFF_WDS, bds, nullptr, nullptr,
        nullptr, D, nullptr, nullptr, MROWS, ADIM, CDIM, 1.0f);
    gemm_mma<0, false><<<gC, 256, GEMM_SMEM>>>(D, W + OFF_WUS, bus, nullptr, out,
        out, nullptr, nullptr, nullptr, MROWS, CDIM, ADIM, 1.0f);
}